// round 9
// baseline (speedup 1.0000x reference)
#include <cuda_runtime.h>
#include <cuda_bf16.h>
#include <math.h>
#include <stdint.h>

#define B 2
#define S 2048
#define D 2048
#define H 16
#define KVH 4
#define HD 128
#define GROUPS (H/KVH)
#define SCALE 0.08838834764831845f
#define M_ROWS (B*S)          // 4096

// ---------------- scratch (__device__ globals; no allocation) --------------
__device__ float g_Q[B*S*H*HD];
__device__ float g_K[B*S*KVH*HD];

__device__ __nv_bfloat16 g_xhi[M_ROWS*D],  g_xlo[M_ROWS*D];
__device__ __nv_bfloat16 g_ohi[M_ROWS*D],  g_olo[M_ROWS*D];
__device__ __nv_bfloat16 g_WqT_hi[D*H*HD],   g_WqT_lo[D*H*HD];
__device__ __nv_bfloat16 g_WkT_hi[D*KVH*HD], g_WkT_lo[D*KVH*HD];
__device__ __nv_bfloat16 g_WvT_hi[D*KVH*HD], g_WvT_lo[D*KVH*HD];
__device__ __nv_bfloat16 g_WoT_hi[D*H*HD],   g_WoT_lo[D*H*HD];

__device__ __nv_bfloat16 g_Qhi[B*S*H*HD],   g_Qlo[B*S*H*HD];
__device__ __nv_bfloat16 g_Khi[B*S*KVH*HD], g_Klo[B*S*KVH*HD];
__device__ __nv_bfloat16 g_Vhi[B*S*KVH*HD], g_Vlo[B*S*KVH*HD];

// ---------------------------- helpers --------------------------------------
__device__ __forceinline__ uint32_t smem_u32(const void* p) {
    uint32_t a;
    asm("{ .reg .u64 t; cvta.to.shared.u64 t, %1; cvt.u32.u64 %0, t; }"
        : "=r"(a) : "l"(p));
    return a;
}
__device__ __forceinline__ void cp16(uint32_t s, const void* g) {
    asm volatile("cp.async.cg.shared.global [%0], [%1], 16;" :: "r"(s), "l"(g));
}
#define CP_COMMIT() asm volatile("cp.async.commit_group;" ::: "memory")
#define CP_WAIT(n)  asm volatile("cp.async.wait_group %0;" :: "n"(n) : "memory")

__device__ __forceinline__ void mma16816(float* c, const uint32_t* a,
                                         const uint32_t* b) {
    asm volatile(
        "mma.sync.aligned.m16n8k16.row.col.f32.bf16.bf16.f32 "
        "{%0,%1,%2,%3}, {%4,%5,%6,%7}, {%8,%9}, {%0,%1,%2,%3};"
        : "+f"(c[0]), "+f"(c[1]), "+f"(c[2]), "+f"(c[3])
        : "r"(a[0]), "r"(a[1]), "r"(a[2]), "r"(a[3]), "r"(b[0]), "r"(b[1]));
}
__device__ __forceinline__ void ldmx4(uint32_t* r, uint32_t addr) {
    asm volatile("ldmatrix.sync.aligned.m8n8.x4.shared.b16 {%0,%1,%2,%3}, [%4];"
        : "=r"(r[0]), "=r"(r[1]), "=r"(r[2]), "=r"(r[3]) : "r"(addr));
}
__device__ __forceinline__ void ldmx4t(uint32_t* r, uint32_t addr) {
    asm volatile("ldmatrix.sync.aligned.m8n8.x4.trans.shared.b16 "
                 "{%0,%1,%2,%3}, [%4];"
        : "=r"(r[0]), "=r"(r[1]), "=r"(r[2]), "=r"(r[3]) : "r"(addr));
}
__device__ __forceinline__ uint32_t packbf(float lo_e, float hi_e) {
    uint32_t d;
    asm("cvt.rn.bf16x2.f32 %0, %1, %2;" : "=r"(d) : "f"(hi_e), "f"(lo_e));
    return d;
}
__device__ __forceinline__ float bf16hi(float x) {
    return __bfloat162float(__float2bfloat16_rn(x));
}

// ---------------------------------------------------------------------------
// split: fp32 -> (hi, lo) bf16
// ---------------------------------------------------------------------------
__global__ void split_kernel(const float* __restrict__ X,
                             __nv_bfloat16* __restrict__ hi,
                             __nv_bfloat16* __restrict__ lo, int n4)
{
    int i = blockIdx.x * blockDim.x + threadIdx.x;
    if (i >= n4) return;
    float4 x = reinterpret_cast<const float4*>(X)[i];
    __nv_bfloat16 h[4], l[4];
    float xs[4] = {x.x, x.y, x.z, x.w};
    #pragma unroll
    for (int k = 0; k < 4; k++) {
        h[k] = __float2bfloat16_rn(xs[k]);
        l[k] = __float2bfloat16_rn(xs[k] - __bfloat162float(h[k]));
    }
    *reinterpret_cast<uint2*>(hi + 4*(size_t)i) = *reinterpret_cast<uint2*>(h);
    *reinterpret_cast<uint2*>(lo + 4*(size_t)i) = *reinterpret_cast<uint2*>(l);
}

// ---------------------------------------------------------------------------
// rope + split (+ optional scale)
// ---------------------------------------------------------------------------
__global__ void rope_split_kernel(const float* __restrict__ X,
                                  const float* __restrict__ cosb,
                                  const float* __restrict__ sinb,
                                  __nv_bfloat16* __restrict__ hi,
                                  __nv_bfloat16* __restrict__ lo,
                                  float scale, int nheads)
{
    int idx = blockIdx.x * blockDim.x + threadIdx.x;
    int half = idx & 63;
    int s = (idx >> 6) / nheads % S;
    size_t base = (size_t)(idx >> 6) * HD;
    float x0 = X[base + half];
    float x1 = X[base + half + 64];
    float c0 = cosb[s * 64 + (half >> 1)];
    float s0 = sinb[s * 64 + (half >> 1)];
    float c1 = cosb[s * 64 + ((half + 64) >> 1)];
    float s1 = sinb[s * 64 + ((half + 64) >> 1)];
    float y0 = (x0 * c0 - x1 * s0) * scale;
    float y1 = (x1 * c1 + x0 * s1) * scale;
    float h0 = bf16hi(y0), h1 = bf16hi(y1);
    hi[base + half]      = __float2bfloat16_rn(h0);
    hi[base + half + 64] = __float2bfloat16_rn(h1);
    lo[base + half]      = __float2bfloat16_rn(y0 - h0);
    lo[base + half + 64] = __float2bfloat16_rn(y1 - h1);
}

// ---------------------------------------------------------------------------
// transpose + split: W [R, C] fp32 -> T{hi,lo} [C, R] bf16.
// z dimension selects among up to 2 (W, Thi, Tlo) triples (for merged K/V).
// ---------------------------------------------------------------------------
__global__ void transpose_split_kernel(const float* __restrict__ W0,
                                       __nv_bfloat16* __restrict__ Thi0,
                                       __nv_bfloat16* __restrict__ Tlo0,
                                       const float* __restrict__ W1,
                                       __nv_bfloat16* __restrict__ Thi1,
                                       __nv_bfloat16* __restrict__ Tlo1,
                                       int R, int C)
{
    const float* W = blockIdx.z ? W1 : W0;
    __nv_bfloat16* Thi = blockIdx.z ? Thi1 : Thi0;
    __nv_bfloat16* Tlo = blockIdx.z ? Tlo1 : Tlo0;
    __shared__ float t[32][33];
    int c0 = blockIdx.x * 32, r0 = blockIdx.y * 32;
    int tx = threadIdx.x, ty = threadIdx.y;
    #pragma unroll
    for (int i = 0; i < 32; i += 8)
        t[ty + i][tx] = W[(size_t)(r0 + ty + i) * C + c0 + tx];
    __syncthreads();
    #pragma unroll
    for (int i = 0; i < 32; i += 8) {
        float x = t[tx][ty + i];
        size_t o = (size_t)(c0 + ty + i) * R + r0 + tx;
        __nv_bfloat16 h = __float2bfloat16_rn(x);
        Thi[o] = h;
        Tlo[o] = __float2bfloat16_rn(x - __bfloat162float(h));
    }
}

// ---------------------------------------------------------------------------
// HMMA bf16x3 GEMM, ldmatrix fragments, BK=32, 2-stage, 2 CTAs/SM.
// CTA 128x128, 8 warps (2x4), warp tile 64x32.
// If Shi != nullptr: write bf16 hi/lo split instead of fp32 C.
// ---------------------------------------------------------------------------
#define ASTR 40
#define MAT_SZ (128*ASTR)
#define STG_SZ (4*MAT_SZ)
#define GEMM_SMEM (2*STG_SZ*2)     // 81920 bytes

__global__ __launch_bounds__(256, 2)
void gemm_bf16x3_kernel(float* __restrict__ C,
    __nv_bfloat16* __restrict__ Shi, __nv_bfloat16* __restrict__ Slo,
    const __nv_bfloat16* __restrict__ Ahi, const __nv_bfloat16* __restrict__ Alo,
    const __nv_bfloat16* __restrict__ Bhi, const __nv_bfloat16* __restrict__ Blo,
    int M, int N, int K)
{
    extern __shared__ __nv_bfloat16 smb[];
    const uint32_t smem_base = smem_u32(smb);
    const int tid = threadIdx.x;
    const int wid = tid >> 5, lane = tid & 31;
    const int g = lane >> 2, tig = lane & 3;
    const int wm = wid >> 2, wn = wid & 3;
    const int m0 = blockIdx.y * 128, n0 = blockIdx.x * 128;
    const int nch = K >> 5;

    const int rowselA = ((lane >> 3) & 1) * 8 + (lane & 7);
    const int colselA = ((lane >> 4) & 1) * 8;
    const int bcolsel = ((lane >> 4) & 1) * 8 + (lane & 7);
    const int bksel   = ((lane >> 3) & 1) * 8;

    const __nv_bfloat16* gsrc[4] = {Ahi, Alo, Bhi, Blo};

    auto load_chunk = [&](int c, int stage) {
        const int k0 = c << 5;
        #pragma unroll
        for (int i = 0; i < 8; ++i) {
            int v = i * 256 + tid;            // 0..2047
            int mat = v >> 9;                 // 0..3
            int r = (v >> 2) & 127;
            int ch = v & 3;
            int grow = (mat < 2 ? m0 : n0) + r;
            const __nv_bfloat16* src = gsrc[mat] + (size_t)grow * K + k0 + ch * 8;
            uint32_t dst = smem_base +
                (uint32_t)(stage * STG_SZ + mat * MAT_SZ + r * ASTR + ch * 8) * 2;
            cp16(dst, src);
        }
    };

    float acc[4][4][4];
    #pragma unroll
    for (int mi = 0; mi < 4; mi++)
        #pragma unroll
        for (int ni = 0; ni < 4; ni++)
            #pragma unroll
            for (int r = 0; r < 4; r++) acc[mi][ni][r] = 0.f;

    load_chunk(0, 0);
    CP_COMMIT();

    for (int c = 0; c < nch; ++c) {
        if (c + 1 < nch) { load_chunk(c + 1, (c + 1) & 1); CP_COMMIT(); CP_WAIT(1); }
        else             { CP_WAIT(0); }
        __syncthreads();

        const uint32_t stg = smem_base + (uint32_t)((c & 1) * STG_SZ) * 2;
        const uint32_t bAh = stg;
        const uint32_t bAl = stg + (uint32_t)MAT_SZ * 2;
        const uint32_t bBh = stg + (uint32_t)(2 * MAT_SZ) * 2;
        const uint32_t bBl = stg + (uint32_t)(3 * MAT_SZ) * 2;

        #pragma unroll
        for (int ks = 0; ks < 2; ++ks) {
            const int kk0 = ks * 16;
            uint32_t Ah[4][4], Al[4][4], Bh[2][4], Bl[2][4];
            #pragma unroll
            for (int mi = 0; mi < 4; ++mi) {
                uint32_t ar = (uint32_t)((wm * 64 + mi * 16 + rowselA) * ASTR
                                         + kk0 + colselA) * 2;
                ldmx4(Ah[mi], bAh + ar);
                ldmx4(Al[mi], bAl + ar);
            }
            #pragma unroll
            for (int nip = 0; nip < 2; ++nip) {
                uint32_t br = (uint32_t)((wn * 32 + nip * 16 + bcolsel) * ASTR
                                         + kk0 + bksel) * 2;
                ldmx4(Bh[nip], bBh + br);
                ldmx4(Bl[nip], bBl + br);
            }
            #pragma unroll
            for (int mi = 0; mi < 4; ++mi)
                #pragma unroll
                for (int ni = 0; ni < 4; ++ni) {
                    const uint32_t* bh = &Bh[ni >> 1][(ni & 1) * 2];
                    const uint32_t* bl = &Bl[ni >> 1][(ni & 1) * 2];
                    mma16816(acc[mi][ni], Ah[mi], bh);
                    mma16816(acc[mi][ni], Ah[mi], bl);
                    mma16816(acc[mi][ni], Al[mi], bh);
                }
        }
        __syncthreads();
    }

    if (Shi) {
        #pragma unroll
        for (int mi = 0; mi < 4; ++mi) {
            int rm = m0 + wm * 64 + mi * 16 + g;
            #pragma unroll
            for (int ni = 0; ni < 4; ++ni) {
                int cn = n0 + wn * 32 + ni * 8 + 2 * tig;
                float v0 = acc[mi][ni][0], v1 = acc[mi][ni][1];
                float v2 = acc[mi][ni][2], v3 = acc[mi][ni][3];
                float h0 = bf16hi(v0), h1 = bf16hi(v1);
                float h2 = bf16hi(v2), h3 = bf16hi(v3);
                *(uint32_t*)(Shi + (size_t)rm * N + cn) = packbf(h0, h1);
                *(uint32_t*)(Slo + (size_t)rm * N + cn) = packbf(v0 - h0, v1 - h1);
                *(uint32_t*)(Shi + (size_t)(rm + 8) * N + cn) = packbf(h2, h3);
                *(uint32_t*)(Slo + (size_t)(rm + 8) * N + cn) = packbf(v2 - h2, v3 - h3);
            }
        }
    } else {
        #pragma unroll
        for (int mi = 0; mi < 4; ++mi) {
            int rm = m0 + wm * 64 + mi * 16 + g;
            #pragma unroll
            for (int ni = 0; ni < 4; ++ni) {
                int cn = n0 + wn * 32 + ni * 8 + 2 * tig;
                *(float2*)(C + (size_t)rm * N + cn) =
                    make_float2(acc[mi][ni][0], acc[mi][ni][1]);
                *(float2*)(C + (size_t)(rm + 8) * N + cn) =
                    make_float2(acc[mi][ni][2], acc[mi][ni][3]);
            }
        }
    }
}

// ---------------------------------------------------------------------------
// FA2-style HMMA flash attention (m_tile order reversed for load balance).
// ---------------------------------------------------------------------------
#define QSF 136
#define STG_KV (4*64*QSF*2)
#define OFF_KV 69632
#define FLASH_SMEM (OFF_KV + 2*STG_KV)   // 208896 bytes

__global__ __launch_bounds__(256, 1) void flash_hmma_kernel(
    const __nv_bfloat16* __restrict__ Qhi, const __nv_bfloat16* __restrict__ Qlo,
    const __nv_bfloat16* __restrict__ Khi, const __nv_bfloat16* __restrict__ Klo,
    const __nv_bfloat16* __restrict__ Vhi, const __nv_bfloat16* __restrict__ Vlo,
    __nv_bfloat16* __restrict__ Ohi, __nv_bfloat16* __restrict__ Olo)
{
    const int m_tile = gridDim.x - 1 - blockIdx.x;   // heavy CTAs first
    const int h = blockIdx.y;
    const int b = blockIdx.z;
    const int kvh = h / GROUPS;
    const int tid = threadIdx.x;
    const int warp = tid >> 5, lane = tid & 31;
    const int g = lane >> 2, tig = lane & 3;
    const int m0 = m_tile * 128;
    const int wrow = warp * 16;

    extern __shared__ char smc[];
    const uint32_t base = smem_u32(smc);

    const int rowselA = ((lane >> 3) & 1) * 8 + (lane & 7);
    const int colselA = ((lane >> 4) & 1) * 8;
    const int bcolsel = ((lane >> 4) & 1) * 8 + (lane & 7);
    const int bksel   = ((lane >> 3) & 1) * 8;
    const uint32_t voff = (uint32_t)(((lane & 7) + ((lane >> 3) & 1) * 8) * QSF
                                     + (lane >> 4) * 8);

    const __nv_bfloat16* kvsrc[4] = {Khi, Klo, Vhi, Vlo};
    auto load_kv = [&](int nt, int stage) {
        const int n0 = nt * 64;
        const uint32_t sb = base + OFF_KV + (uint32_t)stage * STG_KV;
        #pragma unroll
        for (int i = 0; i < 16; ++i) {
            int v = i * 256 + tid;
            int mat = v >> 10;
            int r = (v >> 4) & 63;
            int ch = v & 15;
            const __nv_bfloat16* src = kvsrc[mat]
                + (((size_t)b * S + n0 + r) * KVH + kvh) * HD + ch * 8;
            cp16(sb + (uint32_t)(mat * (64 * QSF) + r * QSF + ch * 8) * 2, src);
        }
    };

    #pragma unroll
    for (int i = 0; i < 16; ++i) {
        int v = i * 256 + tid;
        int mat = v >> 11;
        int r = (v >> 4) & 127;
        int ch = v & 15;
        const __nv_bfloat16* src = (mat ? Qlo : Qhi)
            + (((size_t)b * S + m0 + r) * H + h) * HD + ch * 8;
        cp16(base + (uint32_t)(mat * (128 * QSF) + r * QSF + ch * 8) * 2, src);
    }
    load_kv(0, 0);
    CP_COMMIT();

    float acc[16][4];
    #pragma unroll
    for (int ni = 0; ni < 16; ++ni)
        #pragma unroll
        for (int r = 0; r < 4; ++r) acc[ni][r] = 0.f;

    float m_run0 = -1e30f, m_run1 = -1e30f;
    float l_run0 = 0.f, l_run1 = 0.f;

    const int ntmax = 2 * m_tile + 1;
    for (int nt = 0; nt <= ntmax; ++nt) {
        const int n0 = nt * 64;
        if (nt < ntmax) { load_kv(nt + 1, (nt + 1) & 1); CP_COMMIT(); CP_WAIT(1); }
        else            { CP_WAIT(0); }
        __syncthreads();

        const uint32_t kvb = base + OFF_KV + (uint32_t)(nt & 1) * STG_KV;
        const uint32_t bKh = kvb;
        const uint32_t bKl = kvb + (uint32_t)(64 * QSF) * 2;
        const uint32_t bVh = kvb + (uint32_t)(2 * 64 * QSF) * 2;
        const uint32_t bVl = kvb + (uint32_t)(3 * 64 * QSF) * 2;

        float cs[8][4];
        #pragma unroll
        for (int ni = 0; ni < 8; ++ni)
            #pragma unroll
            for (int r = 0; r < 4; ++r) cs[ni][r] = 0.f;

        #pragma unroll
        for (int ks = 0; ks < 8; ++ks) {
            const int kk0 = ks * 16;
            uint32_t qh[4], ql[4];
            uint32_t ar = (uint32_t)((wrow + rowselA) * QSF + kk0 + colselA) * 2;
            ldmx4(qh, base + ar);
            ldmx4(ql, base + (uint32_t)(128 * QSF) * 2 + ar);
            #pragma unroll
            for (int nip = 0; nip < 4; ++nip) {
                uint32_t kh[4], kl[4];
                uint32_t br = (uint32_t)((nip * 16 + bcolsel) * QSF + kk0 + bksel) * 2;
                ldmx4(kh, bKh + br);
                ldmx4(kl, bKl + br);
                mma16816(cs[2 * nip],     qh, kh);
                mma16816(cs[2 * nip],     qh, kl);
                mma16816(cs[2 * nip],     ql, kh);
                mma16816(cs[2 * nip + 1], qh, kh + 2);
                mma16816(cs[2 * nip + 1], qh, kl + 2);
                mma16816(cs[2 * nip + 1], ql, kh + 2);
            }
        }

        const int r0g = m0 + wrow + g;
        const int colb = n0 + 2 * tig;
        #pragma unroll
        for (int ni = 0; ni < 8; ++ni) {
            int c = colb + ni * 8;
            if (c > r0g)         cs[ni][0] = -1e30f;
            if (c + 1 > r0g)     cs[ni][1] = -1e30f;
            if (c > r0g + 8)     cs[ni][2] = -1e30f;
            if (c + 1 > r0g + 8) cs[ni][3] = -1e30f;
        }

        float mx0 = -1e30f, mx1 = -1e30f;
        #pragma unroll
        for (int ni = 0; ni < 8; ++ni) {
            mx0 = fmaxf(mx0, fmaxf(cs[ni][0], cs[ni][1]));
            mx1 = fmaxf(mx1, fmaxf(cs[ni][2], cs[ni][3]));
        }
        mx0 = fmaxf(mx0, __shfl_xor_sync(0xFFFFFFFFu, mx0, 1));
        mx0 = fmaxf(mx0, __shfl_xor_sync(0xFFFFFFFFu, mx0, 2));
        mx1 = fmaxf(mx1, __shfl_xor_sync(0xFFFFFFFFu, mx1, 1));
        mx1 = fmaxf(mx1, __shfl_xor_sync(0xFFFFFFFFu, mx1, 2));
        const float mn0 = fmaxf(m_run0, mx0);
        const float mn1 = fmaxf(m_run1, mx1);
        const float corr0 = __expf(m_run0 - mn0);
        const float corr1 = __expf(m_run1 - mn1);
        float sum0 = 0.f, sum1 = 0.f;
        #pragma unroll
        for (int ni = 0; ni < 8; ++ni) {
            cs[ni][0] = __expf(cs[ni][0] - mn0); sum0 += cs[ni][0];
            cs[ni][1] = __expf(cs[ni][1] - mn0); sum0 += cs[ni][1];
            cs[ni][2] = __expf(cs[ni][2] - mn1); sum1 += cs[ni][2];
            cs[ni][3] = __expf(cs[ni][3] - mn1); sum1 += cs[ni][3];
        }
        sum0 += __shfl_xor_sync(0xFFFFFFFFu, sum0, 1);
        sum0 += __shfl_xor_sync(0xFFFFFFFFu, sum0, 2);
        sum1 += __shfl_xor_sync(0xFFFFFFFFu, sum1, 1);
        sum1 += __shfl_xor_sync(0xFFFFFFFFu, sum1, 2);
        l_run0 = l_run0 * corr0 + sum0;
        l_run1 = l_run1 * corr1 + sum1;
        m_run0 = mn0;
        m_run1 = mn1;
        #pragma unroll
        for (int ni = 0; ni < 16; ++ni) {
            acc[ni][0] *= corr0; acc[ni][1] *= corr0;
            acc[ni][2] *= corr1; acc[ni][3] *= corr1;
        }

        #pragma unroll
        for (int kp = 0; kp < 4; ++kp) {
            uint32_t aph[4], apl[4];
            #pragma unroll
            for (int t = 0; t < 4; ++t) {
                int nn = 2 * kp + (t >> 1);
                int j0 = (t & 1) * 2;
                float p0 = cs[nn][j0], p1 = cs[nn][j0 + 1];
                float h0 = bf16hi(p0), h1 = bf16hi(p1);
                aph[t] = packbf(h0, h1);
                apl[t] = packbf(p0 - h0, p1 - h1);
            }
            #pragma unroll
            for (int np = 0; np < 8; ++np) {
                uint32_t bh[4], bl[4];
                uint32_t va = (uint32_t)(voff + kp * 16 * QSF + np * 16) * 2;
                ldmx4t(bh, bVh + va);
                ldmx4t(bl, bVl + va);
                mma16816(acc[2 * np],     aph, bh);
                mma16816(acc[2 * np],     aph, bl);
                mma16816(acc[2 * np],     apl, bh);
                mma16816(acc[2 * np + 1], aph, bh + 2);
                mma16816(acc[2 * np + 1], aph, bl + 2);
                mma16816(acc[2 * np + 1], apl, bh + 2);
            }
        }
        __syncthreads();
    }

    const float inv0 = 1.f / l_run0;
    const float inv1 = 1.f / l_run1;
    const size_t row0 = (size_t)b * S + m0 + wrow + g;
    __nv_bfloat16* oh0 = Ohi + row0 * (H * HD) + h * HD;
    __nv_bfloat16* ol0 = Olo + row0 * (H * HD) + h * HD;
    __nv_bfloat16* oh1 = oh0 + 8 * (size_t)(H * HD);
    __nv_bfloat16* ol1 = ol0 + 8 * (size_t)(H * HD);
    #pragma unroll
    for (int ni = 0; ni < 16; ++ni) {
        int c = ni * 8 + 2 * tig;
        float o0 = acc[ni][0] * inv0, o1 = acc[ni][1] * inv0;
        float o2 = acc[ni][2] * inv1, o3 = acc[ni][3] * inv1;
        float h0 = bf16hi(o0), h1 = bf16hi(o1);
        float h2 = bf16hi(o2), h3 = bf16hi(o3);
        *(uint32_t*)(oh0 + c) = packbf(h0, h1);
        *(uint32_t*)(ol0 + c) = packbf(o0 - h0, o1 - h1);
        *(uint32_t*)(oh1 + c) = packbf(h2, h3);
        *(uint32_t*)(ol1 + c) = packbf(o2 - h2, o3 - h3);
    }
}

// ---------------------------------------------------------------------------
extern "C" void kernel_launch(void* const* d_in, const int* in_sizes, int n_in,
                              void* d_out, int out_size)
{
    const float* x    = (const float*)d_in[0];
    const float* cosb = (const float*)d_in[1];
    const float* sinb = (const float*)d_in[2];
    const float* Wq   = (const float*)d_in[4];
    const float* Wk   = (const float*)d_in[5];
    const float* Wv   = (const float*)d_in[6];
    const float* Wo   = (const float*)d_in[7];
    float* out = (float*)d_out;

    float *Qp, *Kp;
    cudaGetSymbolAddress((void**)&Qp, g_Q);
    cudaGetSymbolAddress((void**)&Kp, g_K);
    __nv_bfloat16 *xhi, *xlo, *ohi, *olo;
    __nv_bfloat16 *wqh, *wql, *wkh, *wkl, *wvh, *wvl, *woh, *wol;
    __nv_bfloat16 *qhi, *qlo, *khi, *klo, *vhi, *vlo;
    cudaGetSymbolAddress((void**)&xhi, g_xhi);
    cudaGetSymbolAddress((void**)&xlo, g_xlo);
    cudaGetSymbolAddress((void**)&ohi, g_ohi);
    cudaGetSymbolAddress((void**)&olo, g_olo);
    cudaGetSymbolAddress((void**)&wqh, g_WqT_hi);
    cudaGetSymbolAddress((void**)&wql, g_WqT_lo);
    cudaGetSymbolAddress((void**)&wkh, g_WkT_hi);
    cudaGetSymbolAddress((void**)&wkl, g_WkT_lo);
    cudaGetSymbolAddress((void**)&wvh, g_WvT_hi);
    cudaGetSymbolAddress((void**)&wvl, g_WvT_lo);
    cudaGetSymbolAddress((void**)&woh, g_WoT_hi);
    cudaGetSymbolAddress((void**)&wol, g_WoT_lo);
    cudaGetSymbolAddress((void**)&qhi, g_Qhi);
    cudaGetSymbolAddress((void**)&qlo, g_Qlo);
    cudaGetSymbolAddress((void**)&khi, g_Khi);
    cudaGetSymbolAddress((void**)&klo, g_Klo);
    cudaGetSymbolAddress((void**)&vhi, g_Vhi);
    cudaGetSymbolAddress((void**)&vlo, g_Vlo);

    const int M = M_ROWS;  // 4096

    // prep (ordered so the 5th launch = Q GEMM for ncu capture)
    split_kernel<<<(M * D / 4) / 256, 256>>>(x, xhi, xlo, M * D / 4);
    transpose_split_kernel<<<dim3(D / 32, D / 32), dim3(32, 8)>>>(
        Wq, wqh, wql, nullptr, nullptr, nullptr, D, H * HD);
    transpose_split_kernel<<<dim3((KVH * HD) / 32, D / 32, 2), dim3(32, 8)>>>(
        Wk, wkh, wkl, Wv, wvh, wvl, D, KVH * HD);
    transpose_split_kernel<<<dim3(D / 32, (H * HD) / 32), dim3(32, 8)>>>(
        Wo, woh, wol, nullptr, nullptr, nullptr, H * HD, D);

    cudaFuncSetAttribute(gemm_bf16x3_kernel,
                         cudaFuncAttributeMaxDynamicSharedMemorySize, GEMM_SMEM);

    // projections
    gemm_bf16x3_kernel<<<dim3((H * HD) / 128, M / 128), 256, GEMM_SMEM>>>(
        Qp, nullptr, nullptr, xhi, xlo, wqh, wql, M, H * HD, D);
    gemm_bf16x3_kernel<<<dim3((KVH * HD) / 128, M / 128), 256, GEMM_SMEM>>>(
        Kp, nullptr, nullptr, xhi, xlo, wkh, wkl, M, KVH * HD, D);
    gemm_bf16x3_kernel<<<dim3((KVH * HD) / 128, M / 128), 256, GEMM_SMEM>>>(
        nullptr, vhi, vlo, xhi, xlo, wvh, wvl, M, KVH * HD, D);

    // rope + split
    rope_split_kernel<<<(B * S * H * 64) / 256, 256>>>(
        Qp, cosb, sinb, qhi, qlo, SCALE, H);
    rope_split_kernel<<<(B * S * KVH * 64) / 256, 256>>>(
        Kp, cosb, sinb, khi, klo, 1.0f, KVH);

    // flash attention
    cudaFuncSetAttribute(flash_hmma_kernel,
                         cudaFuncAttributeMaxDynamicSharedMemorySize, FLASH_SMEM);
    flash_hmma_kernel<<<dim3(S / 128, H, B), 256, FLASH_SMEM>>>(
        qhi, qlo, khi, klo, vhi, vlo, ohi, olo);

    // output projection
    gemm_bf16x3_kernel<<<dim3(D / 128, M / 128), 256, GEMM_SMEM>>>(
        out, nullptr, nullptr, ohi, olo, woh, wol, M, D, D);
}

// round 10
// speedup vs baseline: 1.0187x; 1.0187x over previous
#include <cuda_runtime.h>
#include <cuda_bf16.h>
#include <math.h>
#include <stdint.h>

#define B 2
#define S 2048
#define D 2048
#define H 16
#define KVH 4
#define HD 128
#define GROUPS (H/KVH)
#define SCALE 0.08838834764831845f
#define M_ROWS (B*S)          // 4096

// ---------------- scratch (__device__ globals; no allocation) --------------
__device__ float g_Q[B*S*H*HD];
__device__ float g_K[B*S*KVH*HD];

__device__ __nv_bfloat16 g_xhi[M_ROWS*D],  g_xlo[M_ROWS*D];
__device__ __nv_bfloat16 g_ohi[M_ROWS*D],  g_olo[M_ROWS*D];
__device__ __nv_bfloat16 g_WqT_hi[D*H*HD],   g_WqT_lo[D*H*HD];
__device__ __nv_bfloat16 g_WkT_hi[D*KVH*HD], g_WkT_lo[D*KVH*HD];
__device__ __nv_bfloat16 g_WvT_hi[D*KVH*HD], g_WvT_lo[D*KVH*HD];
__device__ __nv_bfloat16 g_WoT_hi[D*H*HD],   g_WoT_lo[D*H*HD];

__device__ __nv_bfloat16 g_Qhi[B*S*H*HD],   g_Qlo[B*S*H*HD];
__device__ __nv_bfloat16 g_Khi[B*S*KVH*HD], g_Klo[B*S*KVH*HD];
__device__ __nv_bfloat16 g_Vhi[B*S*KVH*HD], g_Vlo[B*S*KVH*HD];

// ---------------------------- helpers --------------------------------------
__device__ __forceinline__ uint32_t smem_u32(const void* p) {
    uint32_t a;
    asm("{ .reg .u64 t; cvta.to.shared.u64 t, %1; cvt.u32.u64 %0, t; }"
        : "=r"(a) : "l"(p));
    return a;
}
__device__ __forceinline__ void cp16(uint32_t s, const void* g) {
    asm volatile("cp.async.cg.shared.global [%0], [%1], 16;" :: "r"(s), "l"(g));
}
#define CP_COMMIT() asm volatile("cp.async.commit_group;" ::: "memory")
#define CP_WAIT(n)  asm volatile("cp.async.wait_group %0;" :: "n"(n) : "memory")

__device__ __forceinline__ void mma16816(float* c, const uint32_t* a,
                                         const uint32_t* b) {
    asm volatile(
        "mma.sync.aligned.m16n8k16.row.col.f32.bf16.bf16.f32 "
        "{%0,%1,%2,%3}, {%4,%5,%6,%7}, {%8,%9}, {%0,%1,%2,%3};"
        : "+f"(c[0]), "+f"(c[1]), "+f"(c[2]), "+f"(c[3])
        : "r"(a[0]), "r"(a[1]), "r"(a[2]), "r"(a[3]), "r"(b[0]), "r"(b[1]));
}
__device__ __forceinline__ void ldmx4(uint32_t* r, uint32_t addr) {
    asm volatile("ldmatrix.sync.aligned.m8n8.x4.shared.b16 {%0,%1,%2,%3}, [%4];"
        : "=r"(r[0]), "=r"(r[1]), "=r"(r[2]), "=r"(r[3]) : "r"(addr));
}
__device__ __forceinline__ void ldmx4t(uint32_t* r, uint32_t addr) {
    asm volatile("ldmatrix.sync.aligned.m8n8.x4.trans.shared.b16 "
                 "{%0,%1,%2,%3}, [%4];"
        : "=r"(r[0]), "=r"(r[1]), "=r"(r[2]), "=r"(r[3]) : "r"(addr));
}
__device__ __forceinline__ uint32_t packbf(float lo_e, float hi_e) {
    uint32_t d;
    asm("cvt.rn.bf16x2.f32 %0, %1, %2;" : "=r"(d) : "f"(hi_e), "f"(lo_e));
    return d;
}
__device__ __forceinline__ float bf16hi(float x) {
    return __bfloat162float(__float2bfloat16_rn(x));
}

// ---------------------------------------------------------------------------
// split: fp32 -> (hi, lo) bf16
// ---------------------------------------------------------------------------
__global__ void split_kernel(const float* __restrict__ X,
                             __nv_bfloat16* __restrict__ hi,
                             __nv_bfloat16* __restrict__ lo, int n4)
{
    int i = blockIdx.x * blockDim.x + threadIdx.x;
    if (i >= n4) return;
    float4 x = reinterpret_cast<const float4*>(X)[i];
    __nv_bfloat16 h[4], l[4];
    float xs[4] = {x.x, x.y, x.z, x.w};
    #pragma unroll
    for (int k = 0; k < 4; k++) {
        h[k] = __float2bfloat16_rn(xs[k]);
        l[k] = __float2bfloat16_rn(xs[k] - __bfloat162float(h[k]));
    }
    *reinterpret_cast<uint2*>(hi + 4*(size_t)i) = *reinterpret_cast<uint2*>(h);
    *reinterpret_cast<uint2*>(lo + 4*(size_t)i) = *reinterpret_cast<uint2*>(l);
}

// ---------------------------------------------------------------------------
// rope + split (+ optional scale)
// ---------------------------------------------------------------------------
__global__ void rope_split_kernel(const float* __restrict__ X,
                                  const float* __restrict__ cosb,
                                  const float* __restrict__ sinb,
                                  __nv_bfloat16* __restrict__ hi,
                                  __nv_bfloat16* __restrict__ lo,
                                  float scale, int nheads)
{
    int idx = blockIdx.x * blockDim.x + threadIdx.x;
    int half = idx & 63;
    int s = (idx >> 6) / nheads % S;
    size_t base = (size_t)(idx >> 6) * HD;
    float x0 = X[base + half];
    float x1 = X[base + half + 64];
    float c0 = cosb[s * 64 + (half >> 1)];
    float s0 = sinb[s * 64 + (half >> 1)];
    float c1 = cosb[s * 64 + ((half + 64) >> 1)];
    float s1 = sinb[s * 64 + ((half + 64) >> 1)];
    float y0 = (x0 * c0 - x1 * s0) * scale;
    float y1 = (x1 * c1 + x0 * s1) * scale;
    float h0 = bf16hi(y0), h1 = bf16hi(y1);
    hi[base + half]      = __float2bfloat16_rn(h0);
    hi[base + half + 64] = __float2bfloat16_rn(h1);
    lo[base + half]      = __float2bfloat16_rn(y0 - h0);
    lo[base + half + 64] = __float2bfloat16_rn(y1 - h1);
}

// ---------------------------------------------------------------------------
// transpose + split: W [R, C] fp32 -> T{hi,lo} [C, R] bf16 (z: up to 2 triples)
// ---------------------------------------------------------------------------
__global__ void transpose_split_kernel(const float* __restrict__ W0,
                                       __nv_bfloat16* __restrict__ Thi0,
                                       __nv_bfloat16* __restrict__ Tlo0,
                                       const float* __restrict__ W1,
                                       __nv_bfloat16* __restrict__ Thi1,
                                       __nv_bfloat16* __restrict__ Tlo1,
                                       int R, int C)
{
    const float* W = blockIdx.z ? W1 : W0;
    __nv_bfloat16* Thi = blockIdx.z ? Thi1 : Thi0;
    __nv_bfloat16* Tlo = blockIdx.z ? Tlo1 : Tlo0;
    __shared__ float t[32][33];
    int c0 = blockIdx.x * 32, r0 = blockIdx.y * 32;
    int tx = threadIdx.x, ty = threadIdx.y;
    #pragma unroll
    for (int i = 0; i < 32; i += 8)
        t[ty + i][tx] = W[(size_t)(r0 + ty + i) * C + c0 + tx];
    __syncthreads();
    #pragma unroll
    for (int i = 0; i < 32; i += 8) {
        float x = t[tx][ty + i];
        size_t o = (size_t)(c0 + ty + i) * R + r0 + tx;
        __nv_bfloat16 h = __float2bfloat16_rn(x);
        Thi[o] = h;
        Tlo[o] = __float2bfloat16_rn(x - __bfloat162float(h));
    }
}

// ---------------------------------------------------------------------------
// HMMA bf16x3 GEMM, ldmatrix fragments, BK=64, 3-stage cp.async pipeline.
// CTA 128x128, 8 warps (2x4), warp tile 64x32, 1 CTA/SM.
// If Shi != nullptr: write bf16 hi/lo split instead of fp32 C.
// ---------------------------------------------------------------------------
#define ASTR 72
#define MAT_SZ (128*ASTR)
#define STG_SZ (4*MAT_SZ)
#define NSTG 3
#define GEMM_SMEM (NSTG*STG_SZ*2)     // 221184 bytes

__global__ __launch_bounds__(256, 1)
void gemm_bf16x3_kernel(float* __restrict__ C,
    __nv_bfloat16* __restrict__ Shi, __nv_bfloat16* __restrict__ Slo,
    const __nv_bfloat16* __restrict__ Ahi, const __nv_bfloat16* __restrict__ Alo,
    const __nv_bfloat16* __restrict__ Bhi, const __nv_bfloat16* __restrict__ Blo,
    int M, int N, int K)
{
    extern __shared__ __nv_bfloat16 smb[];
    const uint32_t smem_base = smem_u32(smb);
    const int tid = threadIdx.x;
    const int wid = tid >> 5, lane = tid & 31;
    const int g = lane >> 2, tig = lane & 3;
    const int wm = wid >> 2, wn = wid & 3;
    const int m0 = blockIdx.y * 128, n0 = blockIdx.x * 128;
    const int nch = K >> 6;

    const int rowselA = ((lane >> 3) & 1) * 8 + (lane & 7);
    const int colselA = ((lane >> 4) & 1) * 8;
    const int bcolsel = ((lane >> 4) & 1) * 8 + (lane & 7);
    const int bksel   = ((lane >> 3) & 1) * 8;

    const __nv_bfloat16* gsrc[4] = {Ahi, Alo, Bhi, Blo};

    auto load_chunk = [&](int c, int stage) {
        const int k0 = c << 6;
        #pragma unroll
        for (int i = 0; i < 16; ++i) {
            int v = i * 256 + tid;
            int mat = v >> 10;
            int r = (v >> 3) & 127;
            int ch = v & 7;
            int grow = (mat < 2 ? m0 : n0) + r;
            const __nv_bfloat16* src = gsrc[mat] + (size_t)grow * K + k0 + ch * 8;
            uint32_t dst = smem_base +
                (uint32_t)(stage * STG_SZ + mat * MAT_SZ + r * ASTR + ch * 8) * 2;
            cp16(dst, src);
        }
    };

    float acc[4][4][4];
    #pragma unroll
    for (int mi = 0; mi < 4; mi++)
        #pragma unroll
        for (int ni = 0; ni < 4; ni++)
            #pragma unroll
            for (int r = 0; r < 4; r++) acc[mi][ni][r] = 0.f;

    load_chunk(0, 0);
    CP_COMMIT();
    if (1 < nch) { load_chunk(1, 1); CP_COMMIT(); }

    for (int c = 0; c < nch; ++c) {
        if (c + 1 < nch) CP_WAIT(1);      // stage c complete, c+1 may be in flight
        else             CP_WAIT(0);
        __syncthreads();                  // also: all warps done with stage (c-1)%3

        if (c + 2 < nch) { load_chunk(c + 2, (c + 2) % NSTG); CP_COMMIT(); }

        const uint32_t stg = smem_base + (uint32_t)((c % NSTG) * STG_SZ) * 2;
        const uint32_t bAh = stg;
        const uint32_t bAl = stg + (uint32_t)MAT_SZ * 2;
        const uint32_t bBh = stg + (uint32_t)(2 * MAT_SZ) * 2;
        const uint32_t bBl = stg + (uint32_t)(3 * MAT_SZ) * 2;

        #pragma unroll
        for (int ks = 0; ks < 4; ++ks) {
            const int kk0 = ks * 16;
            uint32_t Ah[4][4], Al[4][4], Bh[2][4], Bl[2][4];
            #pragma unroll
            for (int mi = 0; mi < 4; ++mi) {
                uint32_t ar = (uint32_t)((wm * 64 + mi * 16 + rowselA) * ASTR
                                         + kk0 + colselA) * 2;
                ldmx4(Ah[mi], bAh + ar);
                ldmx4(Al[mi], bAl + ar);
            }
            #pragma unroll
            for (int nip = 0; nip < 2; ++nip) {
                uint32_t br = (uint32_t)((wn * 32 + nip * 16 + bcolsel) * ASTR
                                         + kk0 + bksel) * 2;
                ldmx4(Bh[nip], bBh + br);
                ldmx4(Bl[nip], bBl + br);
            }
            #pragma unroll
            for (int mi = 0; mi < 4; ++mi)
                #pragma unroll
                for (int ni = 0; ni < 4; ++ni) {
                    const uint32_t* bh = &Bh[ni >> 1][(ni & 1) * 2];
                    const uint32_t* bl = &Bl[ni >> 1][(ni & 1) * 2];
                    mma16816(acc[mi][ni], Ah[mi], bh);
                    mma16816(acc[mi][ni], Ah[mi], bl);
                    mma16816(acc[mi][ni], Al[mi], bh);
                }
        }
        __syncthreads();
    }

    if (Shi) {
        #pragma unroll
        for (int mi = 0; mi < 4; ++mi) {
            int rm = m0 + wm * 64 + mi * 16 + g;
            #pragma unroll
            for (int ni = 0; ni < 4; ++ni) {
                int cn = n0 + wn * 32 + ni * 8 + 2 * tig;
                float v0 = acc[mi][ni][0], v1 = acc[mi][ni][1];
                float v2 = acc[mi][ni][2], v3 = acc[mi][ni][3];
                float h0 = bf16hi(v0), h1 = bf16hi(v1);
                float h2 = bf16hi(v2), h3 = bf16hi(v3);
                *(uint32_t*)(Shi + (size_t)rm * N + cn) = packbf(h0, h1);
                *(uint32_t*)(Slo + (size_t)rm * N + cn) = packbf(v0 - h0, v1 - h1);
                *(uint32_t*)(Shi + (size_t)(rm + 8) * N + cn) = packbf(h2, h3);
                *(uint32_t*)(Slo + (size_t)(rm + 8) * N + cn) = packbf(v2 - h2, v3 - h3);
            }
        }
    } else {
        #pragma unroll
        for (int mi = 0; mi < 4; ++mi) {
            int rm = m0 + wm * 64 + mi * 16 + g;
            #pragma unroll
            for (int ni = 0; ni < 4; ++ni) {
                int cn = n0 + wn * 32 + ni * 8 + 2 * tig;
                *(float2*)(C + (size_t)rm * N + cn) =
                    make_float2(acc[mi][ni][0], acc[mi][ni][1]);
                *(float2*)(C + (size_t)(rm + 8) * N + cn) =
                    make_float2(acc[mi][ni][2], acc[mi][ni][3]);
            }
        }
    }
}

// ---------------------------------------------------------------------------
// FA2-style HMMA flash attention (m_tile order reversed for load balance).
// ---------------------------------------------------------------------------
#define QSF 136
#define STG_KV (4*64*QSF*2)
#define OFF_KV 69632
#define FLASH_SMEM (OFF_KV + 2*STG_KV)   // 208896 bytes

__global__ __launch_bounds__(256, 1) void flash_hmma_kernel(
    const __nv_bfloat16* __restrict__ Qhi, const __nv_bfloat16* __restrict__ Qlo,
    const __nv_bfloat16* __restrict__ Khi, const __nv_bfloat16* __restrict__ Klo,
    const __nv_bfloat16* __restrict__ Vhi, const __nv_bfloat16* __restrict__ Vlo,
    __nv_bfloat16* __restrict__ Ohi, __nv_bfloat16* __restrict__ Olo)
{
    const int m_tile = gridDim.x - 1 - blockIdx.x;   // heavy CTAs first
    const int h = blockIdx.y;
    const int b = blockIdx.z;
    const int kvh = h / GROUPS;
    const int tid = threadIdx.x;
    const int warp = tid >> 5, lane = tid & 31;
    const int g = lane >> 2, tig = lane & 3;
    const int m0 = m_tile * 128;
    const int wrow = warp * 16;

    extern __shared__ char smc[];
    const uint32_t base = smem_u32(smc);

    const int rowselA = ((lane >> 3) & 1) * 8 + (lane & 7);
    const int colselA = ((lane >> 4) & 1) * 8;
    const int bcolsel = ((lane >> 4) & 1) * 8 + (lane & 7);
    const int bksel   = ((lane >> 3) & 1) * 8;
    const uint32_t voff = (uint32_t)(((lane & 7) + ((lane >> 3) & 1) * 8) * QSF
                                     + (lane >> 4) * 8);

    const __nv_bfloat16* kvsrc[4] = {Khi, Klo, Vhi, Vlo};
    auto load_kv = [&](int nt, int stage) {
        const int n0 = nt * 64;
        const uint32_t sb = base + OFF_KV + (uint32_t)stage * STG_KV;
        #pragma unroll
        for (int i = 0; i < 16; ++i) {
            int v = i * 256 + tid;
            int mat = v >> 10;
            int r = (v >> 4) & 63;
            int ch = v & 15;
            const __nv_bfloat16* src = kvsrc[mat]
                + (((size_t)b * S + n0 + r) * KVH + kvh) * HD + ch * 8;
            cp16(sb + (uint32_t)(mat * (64 * QSF) + r * QSF + ch * 8) * 2, src);
        }
    };

    #pragma unroll
    for (int i = 0; i < 16; ++i) {
        int v = i * 256 + tid;
        int mat = v >> 11;
        int r = (v >> 4) & 127;
        int ch = v & 15;
        const __nv_bfloat16* src = (mat ? Qlo : Qhi)
            + (((size_t)b * S + m0 + r) * H + h) * HD + ch * 8;
        cp16(base + (uint32_t)(mat * (128 * QSF) + r * QSF + ch * 8) * 2, src);
    }
    load_kv(0, 0);
    CP_COMMIT();

    float acc[16][4];
    #pragma unroll
    for (int ni = 0; ni < 16; ++ni)
        #pragma unroll
        for (int r = 0; r < 4; ++r) acc[ni][r] = 0.f;

    float m_run0 = -1e30f, m_run1 = -1e30f;
    float l_run0 = 0.f, l_run1 = 0.f;

    const int ntmax = 2 * m_tile + 1;
    for (int nt = 0; nt <= ntmax; ++nt) {
        const int n0 = nt * 64;
        if (nt < ntmax) { load_kv(nt + 1, (nt + 1) & 1); CP_COMMIT(); CP_WAIT(1); }
        else            { CP_WAIT(0); }
        __syncthreads();

        const uint32_t kvb = base + OFF_KV + (uint32_t)(nt & 1) * STG_KV;
        const uint32_t bKh = kvb;
        const uint32_t bKl = kvb + (uint32_t)(64 * QSF) * 2;
        const uint32_t bVh = kvb + (uint32_t)(2 * 64 * QSF) * 2;
        const uint32_t bVl = kvb + (uint32_t)(3 * 64 * QSF) * 2;

        float cs[8][4];
        #pragma unroll
        for (int ni = 0; ni < 8; ++ni)
            #pragma unroll
            for (int r = 0; r < 4; ++r) cs[ni][r] = 0.f;

        #pragma unroll
        for (int ks = 0; ks < 8; ++ks) {
            const int kk0 = ks * 16;
            uint32_t qh[4], ql[4];
            uint32_t ar = (uint32_t)((wrow + rowselA) * QSF + kk0 + colselA) * 2;
            ldmx4(qh, base + ar);
            ldmx4(ql, base + (uint32_t)(128 * QSF) * 2 + ar);
            #pragma unroll
            for (int nip = 0; nip < 4; ++nip) {
                uint32_t kh[4], kl[4];
                uint32_t br = (uint32_t)((nip * 16 + bcolsel) * QSF + kk0 + bksel) * 2;
                ldmx4(kh, bKh + br);
                ldmx4(kl, bKl + br);
                mma16816(cs[2 * nip],     qh, kh);
                mma16816(cs[2 * nip],     qh, kl);
                mma16816(cs[2 * nip],     ql, kh);
                mma16816(cs[2 * nip + 1], qh, kh + 2);
                mma16816(cs[2 * nip + 1], qh, kl + 2);
                mma16816(cs[2 * nip + 1], ql, kh + 2);
            }
        }

        const int r0g = m0 + wrow + g;
        const int colb = n0 + 2 * tig;
        #pragma unroll
        for (int ni = 0; ni < 8; ++ni) {
            int c = colb + ni * 8;
            if (c > r0g)         cs[ni][0] = -1e30f;
            if (c + 1 > r0g)     cs[ni][1] = -1e30f;
            if (c > r0g + 8)     cs[ni][2] = -1e30f;
            if (c + 1 > r0g + 8) cs[ni][3] = -1e30f;
        }

        float mx0 = -1e30f, mx1 = -1e30f;
        #pragma unroll
        for (int ni = 0; ni < 8; ++ni) {
            mx0 = fmaxf(mx0, fmaxf(cs[ni][0], cs[ni][1]));
            mx1 = fmaxf(mx1, fmaxf(cs[ni][2], cs[ni][3]));
        }
        mx0 = fmaxf(mx0, __shfl_xor_sync(0xFFFFFFFFu, mx0, 1));
        mx0 = fmaxf(mx0, __shfl_xor_sync(0xFFFFFFFFu, mx0, 2));
        mx1 = fmaxf(mx1, __shfl_xor_sync(0xFFFFFFFFu, mx1, 1));
        mx1 = fmaxf(mx1, __shfl_xor_sync(0xFFFFFFFFu, mx1, 2));
        const float mn0 = fmaxf(m_run0, mx0);
        const float mn1 = fmaxf(m_run1, mx1);
        const float corr0 = __expf(m_run0 - mn0);
        const float corr1 = __expf(m_run1 - mn1);
        float sum0 = 0.f, sum1 = 0.f;
        #pragma unroll
        for (int ni = 0; ni < 8; ++ni) {
            cs[ni][0] = __expf(cs[ni][0] - mn0); sum0 += cs[ni][0];
            cs[ni][1] = __expf(cs[ni][1] - mn0); sum0 += cs[ni][1];
            cs[ni][2] = __expf(cs[ni][2] - mn1); sum1 += cs[ni][2];
            cs[ni][3] = __expf(cs[ni][3] - mn1); sum1 += cs[ni][3];
        }
        sum0 += __shfl_xor_sync(0xFFFFFFFFu, sum0, 1);
        sum0 += __shfl_xor_sync(0xFFFFFFFFu, sum0, 2);
        sum1 += __shfl_xor_sync(0xFFFFFFFFu, sum1, 1);
        sum1 += __shfl_xor_sync(0xFFFFFFFFu, sum1, 2);
        l_run0 = l_run0 * corr0 + sum0;
        l_run1 = l_run1 * corr1 + sum1;
        m_run0 = mn0;
        m_run1 = mn1;
        #pragma unroll
        for (int ni = 0; ni < 16; ++ni) {
            acc[ni][0] *= corr0; acc[ni][1] *= corr0;
            acc[ni][2] *= corr1; acc[ni][3] *= corr1;
        }

        #pragma unroll
        for (int kp = 0; kp < 4; ++kp) {
            uint32_t aph[4], apl[4];
            #pragma unroll
            for (int t = 0; t < 4; ++t) {
                int nn = 2 * kp + (t >> 1);
                int j0 = (t & 1) * 2;
                float p0 = cs[nn][j0], p1 = cs[nn][j0 + 1];
                float h0 = bf16hi(p0), h1 = bf16hi(p1);
                aph[t] = packbf(h0, h1);
                apl[t] = packbf(p0 - h0, p1 - h1);
            }
            #pragma unroll
            for (int np = 0; np < 8; ++np) {
                uint32_t bh[4], bl[4];
                uint32_t va = (uint32_t)(voff + kp * 16 * QSF + np * 16) * 2;
                ldmx4t(bh, bVh + va);
                ldmx4t(bl, bVl + va);
                mma16816(acc[2 * np],     aph, bh);
                mma16816(acc[2 * np],     aph, bl);
                mma16816(acc[2 * np],     apl, bh);
                mma16816(acc[2 * np + 1], aph, bh + 2);
                mma16816(acc[2 * np + 1], aph, bl + 2);
                mma16816(acc[2 * np + 1], apl, bh + 2);
            }
        }
        __syncthreads();
    }

    const float inv0 = 1.f / l_run0;
    const float inv1 = 1.f / l_run1;
    const size_t row0 = (size_t)b * S + m0 + wrow + g;
    __nv_bfloat16* oh0 = Ohi + row0 * (H * HD) + h * HD;
    __nv_bfloat16* ol0 = Olo + row0 * (H * HD) + h * HD;
    __nv_bfloat16* oh1 = oh0 + 8 * (size_t)(H * HD);
    __nv_bfloat16* ol1 = ol0 + 8 * (size_t)(H * HD);
    #pragma unroll
    for (int ni = 0; ni < 16; ++ni) {
        int c = ni * 8 + 2 * tig;
        float o0 = acc[ni][0] * inv0, o1 = acc[ni][1] * inv0;
        float o2 = acc[ni][2] * inv1, o3 = acc[ni][3] * inv1;
        float h0 = bf16hi(o0), h1 = bf16hi(o1);
        float h2 = bf16hi(o2), h3 = bf16hi(o3);
        *(uint32_t*)(oh0 + c) = packbf(h0, h1);
        *(uint32_t*)(ol0 + c) = packbf(o0 - h0, o1 - h1);
        *(uint32_t*)(oh1 + c) = packbf(h2, h3);
        *(uint32_t*)(ol1 + c) = packbf(o2 - h2, o3 - h3);
    }
}

// ---------------------------------------------------------------------------
extern "C" void kernel_launch(void* const* d_in, const int* in_sizes, int n_in,
                              void* d_out, int out_size)
{
    const float* x    = (const float*)d_in[0];
    const float* cosb = (const float*)d_in[1];
    const float* sinb = (const float*)d_in[2];
    const float* Wq   = (const float*)d_in[4];
    const float* Wk   = (const float*)d_in[5];
    const float* Wv   = (const float*)d_in[6];
    const float* Wo   = (const float*)d_in[7];
    float* out = (float*)d_out;

    float *Qp, *Kp;
    cudaGetSymbolAddress((void**)&Qp, g_Q);
    cudaGetSymbolAddress((void**)&Kp, g_K);
    __nv_bfloat16 *xhi, *xlo, *ohi, *olo;
    __nv_bfloat16 *wqh, *wql, *wkh, *wkl, *wvh, *wvl, *woh, *wol;
    __nv_bfloat16 *qhi, *qlo, *khi, *klo, *vhi, *vlo;
    cudaGetSymbolAddress((void**)&xhi, g_xhi);
    cudaGetSymbolAddress((void**)&xlo, g_xlo);
    cudaGetSymbolAddress((void**)&ohi, g_ohi);
    cudaGetSymbolAddress((void**)&olo, g_olo);
    cudaGetSymbolAddress((void**)&wqh, g_WqT_hi);
    cudaGetSymbolAddress((void**)&wql, g_WqT_lo);
    cudaGetSymbolAddress((void**)&wkh, g_WkT_hi);
    cudaGetSymbolAddress((void**)&wkl, g_WkT_lo);
    cudaGetSymbolAddress((void**)&wvh, g_WvT_hi);
    cudaGetSymbolAddress((void**)&wvl, g_WvT_lo);
    cudaGetSymbolAddress((void**)&woh, g_WoT_hi);
    cudaGetSymbolAddress((void**)&wol, g_WoT_lo);
    cudaGetSymbolAddress((void**)&qhi, g_Qhi);
    cudaGetSymbolAddress((void**)&qlo, g_Qlo);
    cudaGetSymbolAddress((void**)&khi, g_Khi);
    cudaGetSymbolAddress((void**)&klo, g_Klo);
    cudaGetSymbolAddress((void**)&vhi, g_Vhi);
    cudaGetSymbolAddress((void**)&vlo, g_Vlo);

    const int M = M_ROWS;  // 4096

    // prep
    split_kernel<<<(M * D / 4) / 256, 256>>>(x, xhi, xlo, M * D / 4);
    transpose_split_kernel<<<dim3(D / 32, D / 32), dim3(32, 8)>>>(
        Wq, wqh, wql, nullptr, nullptr, nullptr, D, H * HD);
    transpose_split_kernel<<<dim3((KVH * HD) / 32, D / 32, 2), dim3(32, 8)>>>(
        Wk, wkh, wkl, Wv, wvh, wvl, D, KVH * HD);
    transpose_split_kernel<<<dim3(D / 32, (H * HD) / 32), dim3(32, 8)>>>(
        Wo, woh, wol, nullptr, nullptr, nullptr, H * HD, D);

    cudaFuncSetAttribute(gemm_bf16x3_kernel,
                         cudaFuncAttributeMaxDynamicSharedMemorySize, GEMM_SMEM);

    // projections
    gemm_bf16x3_kernel<<<dim3((H * HD) / 128, M / 128), 256, GEMM_SMEM>>>(
        Qp, nullptr, nullptr, xhi, xlo, wqh, wql, M, H * HD, D);
    gemm_bf16x3_kernel<<<dim3((KVH * HD) / 128, M / 128), 256, GEMM_SMEM>>>(
        Kp, nullptr, nullptr, xhi, xlo, wkh, wkl, M, KVH * HD, D);
    gemm_bf16x3_kernel<<<dim3((KVH * HD) / 128, M / 128), 256, GEMM_SMEM>>>(
        nullptr, vhi, vlo, xhi, xlo, wvh, wvl, M, KVH * HD, D);

    // rope + split
    rope_split_kernel<<<(B * S * H * 64) / 256, 256>>>(
        Qp, cosb, sinb, qhi, qlo, SCALE, H);
    rope_split_kernel<<<(B * S * KVH * 64) / 256, 256>>>(
        Kp, cosb, sinb, khi, klo, 1.0f, KVH);

    // flash attention
    cudaFuncSetAttribute(flash_hmma_kernel,
                         cudaFuncAttributeMaxDynamicSharedMemorySize, FLASH_SMEM);
    flash_hmma_kernel<<<dim3(S / 128, H, B), 256, FLASH_SMEM>>>(
        qhi, qlo, khi, klo, vhi, vlo, ohi, olo);

    // output projection
    gemm_bf16x3_kernel<<<dim3(D / 128, M / 128), 256, GEMM_SMEM>>>(
        out, nullptr, nullptr, ohi, olo, woh, wol, M, D, D);
}

// round 11
// speedup vs baseline: 1.0641x; 1.0445x over previous
#include <cuda_runtime.h>
#include <cuda_bf16.h>
#include <math.h>
#include <stdint.h>

#define B 2
#define S 2048
#define D 2048
#define H 16
#define KVH 4
#define HD 128
#define GROUPS (H/KVH)
#define SCALE 0.08838834764831845f
#define M_ROWS (B*S)          // 4096
#define NQKV (H*HD + 2*KVH*HD)   // 3072

// ---------------- scratch (__device__ globals; no allocation) --------------
__device__ float g_QKV[M_ROWS*NQKV];           // fused projection output

__device__ __nv_bfloat16 g_xhi[M_ROWS*D],  g_xlo[M_ROWS*D];
__device__ __nv_bfloat16 g_ohi[M_ROWS*D],  g_olo[M_ROWS*D];
__device__ __nv_bfloat16 g_WqkvT_hi[NQKV*D], g_WqkvT_lo[NQKV*D];  // [3072,2048]
__device__ __nv_bfloat16 g_WoT_hi[D*H*HD],   g_WoT_lo[D*H*HD];

__device__ __nv_bfloat16 g_Qhi[B*S*H*HD],   g_Qlo[B*S*H*HD];
__device__ __nv_bfloat16 g_Khi[B*S*KVH*HD], g_Klo[B*S*KVH*HD];
__device__ __nv_bfloat16 g_Vhi[B*S*KVH*HD], g_Vlo[B*S*KVH*HD];

// ---------------------------- helpers --------------------------------------
__device__ __forceinline__ uint32_t smem_u32(const void* p) {
    uint32_t a;
    asm("{ .reg .u64 t; cvta.to.shared.u64 t, %1; cvt.u32.u64 %0, t; }"
        : "=r"(a) : "l"(p));
    return a;
}
__device__ __forceinline__ void cp16(uint32_t s, const void* g) {
    asm volatile("cp.async.cg.shared.global [%0], [%1], 16;" :: "r"(s), "l"(g));
}
#define CP_COMMIT() asm volatile("cp.async.commit_group;" ::: "memory")
#define CP_WAIT(n)  asm volatile("cp.async.wait_group %0;" :: "n"(n) : "memory")

__device__ __forceinline__ void mma16816(float* c, const uint32_t* a,
                                         const uint32_t* b) {
    asm volatile(
        "mma.sync.aligned.m16n8k16.row.col.f32.bf16.bf16.f32 "
        "{%0,%1,%2,%3}, {%4,%5,%6,%7}, {%8,%9}, {%0,%1,%2,%3};"
        : "+f"(c[0]), "+f"(c[1]), "+f"(c[2]), "+f"(c[3])
        : "r"(a[0]), "r"(a[1]), "r"(a[2]), "r"(a[3]), "r"(b[0]), "r"(b[1]));
}
__device__ __forceinline__ void ldmx4(uint32_t* r, uint32_t addr) {
    asm volatile("ldmatrix.sync.aligned.m8n8.x4.shared.b16 {%0,%1,%2,%3}, [%4];"
        : "=r"(r[0]), "=r"(r[1]), "=r"(r[2]), "=r"(r[3]) : "r"(addr));
}
__device__ __forceinline__ void ldmx4t(uint32_t* r, uint32_t addr) {
    asm volatile("ldmatrix.sync.aligned.m8n8.x4.trans.shared.b16 "
                 "{%0,%1,%2,%3}, [%4];"
        : "=r"(r[0]), "=r"(r[1]), "=r"(r[2]), "=r"(r[3]) : "r"(addr));
}
__device__ __forceinline__ uint32_t packbf(float lo_e, float hi_e) {
    uint32_t d;
    asm("cvt.rn.bf16x2.f32 %0, %1, %2;" : "=r"(d) : "f"(hi_e), "f"(lo_e));
    return d;
}
__device__ __forceinline__ float bf16hi(float x) {
    return __bfloat162float(__float2bfloat16_rn(x));
}

// ---------------------------------------------------------------------------
// split: fp32 packed -> (hi, lo) bf16 packed
// ---------------------------------------------------------------------------
__global__ void split_kernel(const float* __restrict__ X,
                             __nv_bfloat16* __restrict__ hi,
                             __nv_bfloat16* __restrict__ lo, int n4)
{
    int i = blockIdx.x * blockDim.x + threadIdx.x;
    if (i >= n4) return;
    float4 x = reinterpret_cast<const float4*>(X)[i];
    __nv_bfloat16 h[4], l[4];
    float xs[4] = {x.x, x.y, x.z, x.w};
    #pragma unroll
    for (int k = 0; k < 4; k++) {
        h[k] = __float2bfloat16_rn(xs[k]);
        l[k] = __float2bfloat16_rn(xs[k] - __bfloat162float(h[k]));
    }
    *reinterpret_cast<uint2*>(hi + 4*(size_t)i) = *reinterpret_cast<uint2*>(h);
    *reinterpret_cast<uint2*>(lo + 4*(size_t)i) = *reinterpret_cast<uint2*>(l);
}

// ---------------------------------------------------------------------------
// strided split (for V slice of fused QKV buffer) -> packed bf16 hi/lo
// ---------------------------------------------------------------------------
__global__ void split_strided_kernel(const float* __restrict__ X,
                                     __nv_bfloat16* __restrict__ hi,
                                     __nv_bfloat16* __restrict__ lo,
                                     int width, int srcstride, int coloff, int n4)
{
    int i = blockIdx.x * blockDim.x + threadIdx.x;
    if (i >= n4) return;
    int e0 = i * 4;
    int row = e0 / width, col = e0 % width;
    const float* src = X + (size_t)row * srcstride + coloff + col;
    float4 x = *reinterpret_cast<const float4*>(src);
    __nv_bfloat16 h[4], l[4];
    float xs[4] = {x.x, x.y, x.z, x.w};
    #pragma unroll
    for (int k = 0; k < 4; k++) {
        h[k] = __float2bfloat16_rn(xs[k]);
        l[k] = __float2bfloat16_rn(xs[k] - __bfloat162float(h[k]));
    }
    *reinterpret_cast<uint2*>(hi + (size_t)e0) = *reinterpret_cast<uint2*>(h);
    *reinterpret_cast<uint2*>(lo + (size_t)e0) = *reinterpret_cast<uint2*>(l);
}

// ---------------------------------------------------------------------------
// rope + split with source row stride / col offset (reads fused QKV buffer)
// ---------------------------------------------------------------------------
__global__ void rope_split_kernel(const float* __restrict__ X,
                                  const float* __restrict__ cosb,
                                  const float* __restrict__ sinb,
                                  __nv_bfloat16* __restrict__ hi,
                                  __nv_bfloat16* __restrict__ lo,
                                  float scale, int nheads,
                                  int rowstride, int coloff)
{
    int idx = blockIdx.x * blockDim.x + threadIdx.x;
    int half = idx & 63;
    int hrow = idx >> 6;                  // (b*S+s)*nheads + head
    int rowidx = hrow / nheads;
    int head = hrow - rowidx * nheads;
    int s = rowidx % S;
    const float* src = X + (size_t)rowidx * rowstride + coloff + head * HD;
    size_t dbase = (size_t)hrow * HD;
    float x0 = src[half];
    float x1 = src[half + 64];
    float c0 = cosb[s * 64 + (half >> 1)];
    float s0 = sinb[s * 64 + (half >> 1)];
    float c1 = cosb[s * 64 + ((half + 64) >> 1)];
    float s1 = sinb[s * 64 + ((half + 64) >> 1)];
    float y0 = (x0 * c0 - x1 * s0) * scale;
    float y1 = (x1 * c1 + x0 * s1) * scale;
    float h0 = bf16hi(y0), h1 = bf16hi(y1);
    hi[dbase + half]      = __float2bfloat16_rn(h0);
    hi[dbase + half + 64] = __float2bfloat16_rn(h1);
    lo[dbase + half]      = __float2bfloat16_rn(y0 - h0);
    lo[dbase + half + 64] = __float2bfloat16_rn(y1 - h1);
}

// ---------------------------------------------------------------------------
// transpose + split: W [R, C] fp32 -> T [C, R] bf16 hi/lo (z: up to 2 triples)
// ---------------------------------------------------------------------------
__global__ void transpose_split_kernel(const float* __restrict__ W0,
                                       __nv_bfloat16* __restrict__ Thi0,
                                       __nv_bfloat16* __restrict__ Tlo0,
                                       const float* __restrict__ W1,
                                       __nv_bfloat16* __restrict__ Thi1,
                                       __nv_bfloat16* __restrict__ Tlo1,
                                       int R, int C)
{
    const float* W = blockIdx.z ? W1 : W0;
    __nv_bfloat16* Thi = blockIdx.z ? Thi1 : Thi0;
    __nv_bfloat16* Tlo = blockIdx.z ? Tlo1 : Tlo0;
    __shared__ float t[32][33];
    int c0 = blockIdx.x * 32, r0 = blockIdx.y * 32;
    int tx = threadIdx.x, ty = threadIdx.y;
    #pragma unroll
    for (int i = 0; i < 32; i += 8)
        t[ty + i][tx] = W[(size_t)(r0 + ty + i) * C + c0 + tx];
    __syncthreads();
    #pragma unroll
    for (int i = 0; i < 32; i += 8) {
        float x = t[tx][ty + i];
        size_t o = (size_t)(c0 + ty + i) * R + r0 + tx;
        __nv_bfloat16 h = __float2bfloat16_rn(x);
        Thi[o] = h;
        Tlo[o] = __float2bfloat16_rn(x - __bfloat162float(h));
    }
}

// ---------------------------------------------------------------------------
// HMMA bf16x3 GEMM: CTA 256x128, 8 warps (4x2), warp tile 64x64, BK=64,
// 2-stage cp.async, ldmatrix fragments. Tensor-bound by design
// (fragment smem traffic = 2/3 of MMA time).
// ---------------------------------------------------------------------------
#define ASTR 72
#define STG2 55296                 // bf16 units per stage
#define OFF_ALO 18432
#define OFF_BHI 36864
#define OFF_BLO 46080
#define GEMM_SMEM (2*STG2*2)       // 221184 bytes

__global__ __launch_bounds__(256, 1)
void gemm_bf16x3_kernel(float* __restrict__ C,
    const __nv_bfloat16* __restrict__ Ahi, const __nv_bfloat16* __restrict__ Alo,
    const __nv_bfloat16* __restrict__ Bhi, const __nv_bfloat16* __restrict__ Blo,
    int M, int N, int K)
{
    extern __shared__ __nv_bfloat16 smb[];
    const uint32_t smem_base = smem_u32(smb);
    const int tid = threadIdx.x;
    const int wid = tid >> 5, lane = tid & 31;
    const int g = lane >> 2, tig = lane & 3;
    const int wm = wid >> 1, wn = wid & 1;          // 4 x 2 warp grid
    const int m0 = blockIdx.y * 256, n0 = blockIdx.x * 128;
    const int nch = K >> 6;

    const int rowselA = ((lane >> 3) & 1) * 8 + (lane & 7);
    const int colselA = ((lane >> 4) & 1) * 8;
    const int bcolsel = ((lane >> 4) & 1) * 8 + (lane & 7);
    const int bksel   = ((lane >> 3) & 1) * 8;

    auto load_chunk = [&](int c, int stage) {
        const int k0 = c << 6;
        const uint32_t sb = smem_base + (uint32_t)(stage * STG2) * 2;
        #pragma unroll
        for (int i = 0; i < 8; ++i) {
            int v = i * 256 + tid; int r = v >> 3, ch = v & 7;
            cp16(sb + (uint32_t)(r * ASTR + ch * 8) * 2,
                 Ahi + (size_t)(m0 + r) * K + k0 + ch * 8);
        }
        #pragma unroll
        for (int i = 0; i < 8; ++i) {
            int v = i * 256 + tid; int r = v >> 3, ch = v & 7;
            cp16(sb + (uint32_t)(OFF_ALO + r * ASTR + ch * 8) * 2,
                 Alo + (size_t)(m0 + r) * K + k0 + ch * 8);
        }
        #pragma unroll
        for (int i = 0; i < 4; ++i) {
            int v = i * 256 + tid; int r = v >> 3, ch = v & 7;
            cp16(sb + (uint32_t)(OFF_BHI + r * ASTR + ch * 8) * 2,
                 Bhi + (size_t)(n0 + r) * K + k0 + ch * 8);
            cp16(sb + (uint32_t)(OFF_BLO + r * ASTR + ch * 8) * 2,
                 Blo + (size_t)(n0 + r) * K + k0 + ch * 8);
        }
    };

    float acc[4][8][4];
    #pragma unroll
    for (int mi = 0; mi < 4; mi++)
        #pragma unroll
        for (int ni = 0; ni < 8; ni++)
            #pragma unroll
            for (int r = 0; r < 4; r++) acc[mi][ni][r] = 0.f;

    load_chunk(0, 0);
    CP_COMMIT();

    for (int c = 0; c < nch; ++c) {
        if (c + 1 < nch) { load_chunk(c + 1, (c + 1) & 1); CP_COMMIT(); CP_WAIT(1); }
        else             { CP_WAIT(0); }
        __syncthreads();

        const uint32_t stg = smem_base + (uint32_t)((c & 1) * STG2) * 2;
        const uint32_t bAh = stg;
        const uint32_t bAl = stg + (uint32_t)OFF_ALO * 2;
        const uint32_t bBh = stg + (uint32_t)OFF_BHI * 2;
        const uint32_t bBl = stg + (uint32_t)OFF_BLO * 2;

        #pragma unroll
        for (int ks = 0; ks < 4; ++ks) {
            const int kk0 = ks * 16;
            uint32_t Ah[4][4], Al[4][4], Bh[4][4], Bl[4][4];
            #pragma unroll
            for (int mi = 0; mi < 4; ++mi) {
                uint32_t ar = (uint32_t)((wm * 64 + mi * 16 + rowselA) * ASTR
                                         + kk0 + colselA) * 2;
                ldmx4(Ah[mi], bAh + ar);
                ldmx4(Al[mi], bAl + ar);
            }
            #pragma unroll
            for (int nip = 0; nip < 4; ++nip) {
                uint32_t br = (uint32_t)((wn * 64 + nip * 16 + bcolsel) * ASTR
                                         + kk0 + bksel) * 2;
                ldmx4(Bh[nip], bBh + br);
                ldmx4(Bl[nip], bBl + br);
            }
            #pragma unroll
            for (int mi = 0; mi < 4; ++mi)
                #pragma unroll
                for (int ni = 0; ni < 8; ++ni) {
                    const uint32_t* bh = &Bh[ni >> 1][(ni & 1) * 2];
                    const uint32_t* bl = &Bl[ni >> 1][(ni & 1) * 2];
                    mma16816(acc[mi][ni], Ah[mi], bh);
                    mma16816(acc[mi][ni], Ah[mi], bl);
                    mma16816(acc[mi][ni], Al[mi], bh);
                }
        }
        __syncthreads();
    }

    #pragma unroll
    for (int mi = 0; mi < 4; ++mi) {
        int rm = m0 + wm * 64 + mi * 16 + g;
        #pragma unroll
        for (int ni = 0; ni < 8; ++ni) {
            int cn = n0 + wn * 64 + ni * 8 + 2 * tig;
            *(float2*)(C + (size_t)rm * N + cn) =
                make_float2(acc[mi][ni][0], acc[mi][ni][1]);
            *(float2*)(C + (size_t)(rm + 8) * N + cn) =
                make_float2(acc[mi][ni][2], acc[mi][ni][3]);
        }
    }
}

// ---------------------------------------------------------------------------
// FA2-style HMMA flash attention (unchanged from R7/R10 best).
// ---------------------------------------------------------------------------
#define QSF 136
#define STG_KV (4*64*QSF*2)
#define OFF_KV 69632
#define FLASH_SMEM (OFF_KV + 2*STG_KV)   // 208896 bytes

__global__ __launch_bounds__(256, 1) void flash_hmma_kernel(
    const __nv_bfloat16* __restrict__ Qhi, const __nv_bfloat16* __restrict__ Qlo,
    const __nv_bfloat16* __restrict__ Khi, const __nv_bfloat16* __restrict__ Klo,
    const __nv_bfloat16* __restrict__ Vhi, const __nv_bfloat16* __restrict__ Vlo,
    __nv_bfloat16* __restrict__ Ohi, __nv_bfloat16* __restrict__ Olo)
{
    const int m_tile = gridDim.x - 1 - blockIdx.x;   // heavy CTAs first
    const int h = blockIdx.y;
    const int b = blockIdx.z;
    const int kvh = h / GROUPS;
    const int tid = threadIdx.x;
    const int warp = tid >> 5, lane = tid & 31;
    const int g = lane >> 2, tig = lane & 3;
    const int m0 = m_tile * 128;
    const int wrow = warp * 16;

    extern __shared__ char smc[];
    const uint32_t base = smem_u32(smc);

    const int rowselA = ((lane >> 3) & 1) * 8 + (lane & 7);
    const int colselA = ((lane >> 4) & 1) * 8;
    const int bcolsel = ((lane >> 4) & 1) * 8 + (lane & 7);
    const int bksel   = ((lane >> 3) & 1) * 8;
    const uint32_t voff = (uint32_t)(((lane & 7) + ((lane >> 3) & 1) * 8) * QSF
                                     + (lane >> 4) * 8);

    const __nv_bfloat16* kvsrc[4] = {Khi, Klo, Vhi, Vlo};
    auto load_kv = [&](int nt, int stage) {
        const int n0 = nt * 64;
        const uint32_t sb = base + OFF_KV + (uint32_t)stage * STG_KV;
        #pragma unroll
        for (int i = 0; i < 16; ++i) {
            int v = i * 256 + tid;
            int mat = v >> 10;
            int r = (v >> 4) & 63;
            int ch = v & 15;
            const __nv_bfloat16* src = kvsrc[mat]
                + (((size_t)b * S + n0 + r) * KVH + kvh) * HD + ch * 8;
            cp16(sb + (uint32_t)(mat * (64 * QSF) + r * QSF + ch * 8) * 2, src);
        }
    };

    #pragma unroll
    for (int i = 0; i < 16; ++i) {
        int v = i * 256 + tid;
        int mat = v >> 11;
        int r = (v >> 4) & 127;
        int ch = v & 15;
        const __nv_bfloat16* src = (mat ? Qlo : Qhi)
            + (((size_t)b * S + m0 + r) * H + h) * HD + ch * 8;
        cp16(base + (uint32_t)(mat * (128 * QSF) + r * QSF + ch * 8) * 2, src);
    }
    load_kv(0, 0);
    CP_COMMIT();

    float acc[16][4];
    #pragma unroll
    for (int ni = 0; ni < 16; ++ni)
        #pragma unroll
        for (int r = 0; r < 4; ++r) acc[ni][r] = 0.f;

    float m_run0 = -1e30f, m_run1 = -1e30f;
    float l_run0 = 0.f, l_run1 = 0.f;

    const int ntmax = 2 * m_tile + 1;
    for (int nt = 0; nt <= ntmax; ++nt) {
        const int n0 = nt * 64;
        if (nt < ntmax) { load_kv(nt + 1, (nt + 1) & 1); CP_COMMIT(); CP_WAIT(1); }
        else            { CP_WAIT(0); }
        __syncthreads();

        const uint32_t kvb = base + OFF_KV + (uint32_t)(nt & 1) * STG_KV;
        const uint32_t bKh = kvb;
        const uint32_t bKl = kvb + (uint32_t)(64 * QSF) * 2;
        const uint32_t bVh = kvb + (uint32_t)(2 * 64 * QSF) * 2;
        const uint32_t bVl = kvb + (uint32_t)(3 * 64 * QSF) * 2;

        float cs[8][4];
        #pragma unroll
        for (int ni = 0; ni < 8; ++ni)
            #pragma unroll
            for (int r = 0; r < 4; ++r) cs[ni][r] = 0.f;

        #pragma unroll
        for (int ks = 0; ks < 8; ++ks) {
            const int kk0 = ks * 16;
            uint32_t qh[4], ql[4];
            uint32_t ar = (uint32_t)((wrow + rowselA) * QSF + kk0 + colselA) * 2;
            ldmx4(qh, base + ar);
            ldmx4(ql, base + (uint32_t)(128 * QSF) * 2 + ar);
            #pragma unroll
            for (int nip = 0; nip < 4; ++nip) {
                uint32_t kh[4], kl[4];
                uint32_t br = (uint32_t)((nip * 16 + bcolsel) * QSF + kk0 + bksel) * 2;
                ldmx4(kh, bKh + br);
                ldmx4(kl, bKl + br);
                mma16816(cs[2 * nip],     qh, kh);
                mma16816(cs[2 * nip],     qh, kl);
                mma16816(cs[2 * nip],     ql, kh);
                mma16816(cs[2 * nip + 1], qh, kh + 2);
                mma16816(cs[2 * nip + 1], qh, kl + 2);
                mma16816(cs[2 * nip + 1], ql, kh + 2);
            }
        }

        const int r0g = m0 + wrow + g;
        const int colb = n0 + 2 * tig;
        #pragma unroll
        for (int ni = 0; ni < 8; ++ni) {
            int c = colb + ni * 8;
            if (c > r0g)         cs[ni][0] = -1e30f;
            if (c + 1 > r0g)     cs[ni][1] = -1e30f;
            if (c > r0g + 8)     cs[ni][2] = -1e30f;
            if (c + 1 > r0g + 8) cs[ni][3] = -1e30f;
        }

        float mx0 = -1e30f, mx1 = -1e30f;
        #pragma unroll
        for (int ni = 0; ni < 8; ++ni) {
            mx0 = fmaxf(mx0, fmaxf(cs[ni][0], cs[ni][1]));
            mx1 = fmaxf(mx1, fmaxf(cs[ni][2], cs[ni][3]));
        }
        mx0 = fmaxf(mx0, __shfl_xor_sync(0xFFFFFFFFu, mx0, 1));
        mx0 = fmaxf(mx0, __shfl_xor_sync(0xFFFFFFFFu, mx0, 2));
        mx1 = fmaxf(mx1, __shfl_xor_sync(0xFFFFFFFFu, mx1, 1));
        mx1 = fmaxf(mx1, __shfl_xor_sync(0xFFFFFFFFu, mx1, 2));
        const float mn0 = fmaxf(m_run0, mx0);
        const float mn1 = fmaxf(m_run1, mx1);
        const float corr0 = __expf(m_run0 - mn0);
        const float corr1 = __expf(m_run1 - mn1);
        float sum0 = 0.f, sum1 = 0.f;
        #pragma unroll
        for (int ni = 0; ni < 8; ++ni) {
            cs[ni][0] = __expf(cs[ni][0] - mn0); sum0 += cs[ni][0];
            cs[ni][1] = __expf(cs[ni][1] - mn0); sum0 += cs[ni][1];
            cs[ni][2] = __expf(cs[ni][2] - mn1); sum1 += cs[ni][2];
            cs[ni][3] = __expf(cs[ni][3] - mn1); sum1 += cs[ni][3];
        }
        sum0 += __shfl_xor_sync(0xFFFFFFFFu, sum0, 1);
        sum0 += __shfl_xor_sync(0xFFFFFFFFu, sum0, 2);
        sum1 += __shfl_xor_sync(0xFFFFFFFFu, sum1, 1);
        sum1 += __shfl_xor_sync(0xFFFFFFFFu, sum1, 2);
        l_run0 = l_run0 * corr0 + sum0;
        l_run1 = l_run1 * corr1 + sum1;
        m_run0 = mn0;
        m_run1 = mn1;
        #pragma unroll
        for (int ni = 0; ni < 16; ++ni) {
            acc[ni][0] *= corr0; acc[ni][1] *= corr0;
            acc[ni][2] *= corr1; acc[ni][3] *= corr1;
        }

        #pragma unroll
        for (int kp = 0; kp < 4; ++kp) {
            uint32_t aph[4], apl[4];
            #pragma unroll
            for (int t = 0; t < 4; ++t) {
                int nn = 2 * kp + (t >> 1);
                int j0 = (t & 1) * 2;
                float p0 = cs[nn][j0], p1 = cs[nn][j0 + 1];
                float h0 = bf16hi(p0), h1 = bf16hi(p1);
                aph[t] = packbf(h0, h1);
                apl[t] = packbf(p0 - h0, p1 - h1);
            }
            #pragma unroll
            for (int np = 0; np < 8; ++np) {
                uint32_t bh[4], bl[4];
                uint32_t va = (uint32_t)(voff + kp * 16 * QSF + np * 16) * 2;
                ldmx4t(bh, bVh + va);
                ldmx4t(bl, bVl + va);
                mma16816(acc[2 * np],     aph, bh);
                mma16816(acc[2 * np],     aph, bl);
                mma16816(acc[2 * np],     apl, bh);
                mma16816(acc[2 * np + 1], aph, bh + 2);
                mma16816(acc[2 * np + 1], aph, bl + 2);
                mma16816(acc[2 * np + 1], apl, bh + 2);
            }
        }
        __syncthreads();
    }

    const float inv0 = 1.f / l_run0;
    const float inv1 = 1.f / l_run1;
    const size_t row0 = (size_t)b * S + m0 + wrow + g;
    __nv_bfloat16* oh0 = Ohi + row0 * (H * HD) + h * HD;
    __nv_bfloat16* ol0 = Olo + row0 * (H * HD) + h * HD;
    __nv_bfloat16* oh1 = oh0 + 8 * (size_t)(H * HD);
    __nv_bfloat16* ol1 = ol0 + 8 * (size_t)(H * HD);
    #pragma unroll
    for (int ni = 0; ni < 16; ++ni) {
        int c = ni * 8 + 2 * tig;
        float o0 = acc[ni][0] * inv0, o1 = acc[ni][1] * inv0;
        float o2 = acc[ni][2] * inv1, o3 = acc[ni][3] * inv1;
        float h0 = bf16hi(o0), h1 = bf16hi(o1);
        float h2 = bf16hi(o2), h3 = bf16hi(o3);
        *(uint32_t*)(oh0 + c) = packbf(h0, h1);
        *(uint32_t*)(ol0 + c) = packbf(o0 - h0, o1 - h1);
        *(uint32_t*)(oh1 + c) = packbf(h2, h3);
        *(uint32_t*)(ol1 + c) = packbf(o2 - h2, o3 - h3);
    }
}

// ---------------------------------------------------------------------------
extern "C" void kernel_launch(void* const* d_in, const int* in_sizes, int n_in,
                              void* d_out, int out_size)
{
    const float* x    = (const float*)d_in[0];
    const float* cosb = (const float*)d_in[1];
    const float* sinb = (const float*)d_in[2];
    const float* Wq   = (const float*)d_in[4];
    const float* Wk   = (const float*)d_in[5];
    const float* Wv   = (const float*)d_in[6];
    const float* Wo   = (const float*)d_in[7];
    float* out = (float*)d_out;

    float* QKVp;
    cudaGetSymbolAddress((void**)&QKVp, g_QKV);
    __nv_bfloat16 *xhi, *xlo, *ohi, *olo;
    __nv_bfloat16 *wqkvh, *wqkvl, *woh, *wol;
    __nv_bfloat16 *qhi, *qlo, *khi, *klo, *vhi, *vlo;
    cudaGetSymbolAddress((void**)&xhi, g_xhi);
    cudaGetSymbolAddress((void**)&xlo, g_xlo);
    cudaGetSymbolAddress((void**)&ohi, g_ohi);
    cudaGetSymbolAddress((void**)&olo, g_olo);
    cudaGetSymbolAddress((void**)&wqkvh, g_WqkvT_hi);
    cudaGetSymbolAddress((void**)&wqkvl, g_WqkvT_lo);
    cudaGetSymbolAddress((void**)&woh, g_WoT_hi);
    cudaGetSymbolAddress((void**)&wol, g_WoT_lo);
    cudaGetSymbolAddress((void**)&qhi, g_Qhi);
    cudaGetSymbolAddress((void**)&qlo, g_Qlo);
    cudaGetSymbolAddress((void**)&khi, g_Khi);
    cudaGetSymbolAddress((void**)&klo, g_Klo);
    cudaGetSymbolAddress((void**)&vhi, g_Vhi);
    cudaGetSymbolAddress((void**)&vlo, g_Vlo);

    const int M = M_ROWS;  // 4096

    // prep: split x; transpose weights into combined [3072, 2048] + Wo
    split_kernel<<<(M * D / 4) / 256, 256>>>(x, xhi, xlo, M * D / 4);
    transpose_split_kernel<<<dim3(D / 32, D / 32), dim3(32, 8)>>>(
        Wq, wqkvh, wqkvl, nullptr, nullptr, nullptr, D, H * HD);
    transpose_split_kernel<<<dim3((KVH * HD) / 32, D / 32, 2), dim3(32, 8)>>>(
        Wk, wqkvh + (size_t)(H * HD) * D, wqkvl + (size_t)(H * HD) * D,
        Wv, wqkvh + (size_t)(H * HD + KVH * HD) * D,
            wqkvl + (size_t)(H * HD + KVH * HD) * D, D, KVH * HD);
    transpose_split_kernel<<<dim3(D / 32, (H * HD) / 32), dim3(32, 8)>>>(
        Wo, woh, wol, nullptr, nullptr, nullptr, H * HD, D);

    cudaFuncSetAttribute(gemm_bf16x3_kernel,
                         cudaFuncAttributeMaxDynamicSharedMemorySize, GEMM_SMEM);

    // fused QKV projection: [4096, 3072]
    gemm_bf16x3_kernel<<<dim3(NQKV / 128, M / 256), 256, GEMM_SMEM>>>(
        QKVp, xhi, xlo, wqkvh, wqkvl, M, NQKV, D);

    // rope + split from fused buffer (Q scaled); V strided split
    rope_split_kernel<<<(B * S * H * 64) / 256, 256>>>(
        QKVp, cosb, sinb, qhi, qlo, SCALE, H, NQKV, 0);
    rope_split_kernel<<<(B * S * KVH * 64) / 256, 256>>>(
        QKVp, cosb, sinb, khi, klo, 1.0f, KVH, NQKV, H * HD);
    split_strided_kernel<<<(M * KVH * HD / 4) / 256, 256>>>(
        QKVp, vhi, vlo, KVH * HD, NQKV, H * HD + KVH * HD, M * KVH * HD / 4);

    // flash attention
    cudaFuncSetAttribute(flash_hmma_kernel,
                         cudaFuncAttributeMaxDynamicSharedMemorySize, FLASH_SMEM);
    flash_hmma_kernel<<<dim3(S / 128, H, B), 256, FLASH_SMEM>>>(
        qhi, qlo, khi, klo, vhi, vlo, ohi, olo);

    // output projection (256x128 tile)
    gemm_bf16x3_kernel<<<dim3(D / 128, M / 256), 256, GEMM_SMEM>>>(
        out, ohi, olo, woh, wol, M, D, D);
}

// round 12
// speedup vs baseline: 1.2724x; 1.1958x over previous
#include <cuda_runtime.h>
#include <cuda_bf16.h>
#include <cuda_fp16.h>
#include <math.h>
#include <stdint.h>

#define B 2
#define S 2048
#define D 2048
#define H 16
#define KVH 4
#define HD 128
#define GROUPS (H/KVH)
#define SCALE 0.08838834764831845f
#define M_ROWS (B*S)          // 4096
#define NQKV (H*HD + 2*KVH*HD)   // 3072

// ---------------- scratch (__device__ globals; no allocation) --------------
__device__ float g_QKV[M_ROWS*NQKV];           // fused projection output

__device__ __nv_bfloat16 g_xhi[M_ROWS*D],  g_xlo[M_ROWS*D];
__device__ __nv_bfloat16 g_WqkvT_hi[NQKV*D], g_WqkvT_lo[NQKV*D];  // [3072,2048]
__device__ __half g_Wo16T[D*H*HD];             // [2048,2048] fp16
__device__ __half g_O16[M_ROWS*D];             // flash output, fp16

__device__ __nv_bfloat16 g_Qhi[B*S*H*HD],   g_Qlo[B*S*H*HD];
__device__ __nv_bfloat16 g_Khi[B*S*KVH*HD], g_Klo[B*S*KVH*HD];
__device__ __nv_bfloat16 g_Vhi[B*S*KVH*HD], g_Vlo[B*S*KVH*HD];

// ---------------------------- helpers --------------------------------------
__device__ __forceinline__ uint32_t smem_u32(const void* p) {
    uint32_t a;
    asm("{ .reg .u64 t; cvta.to.shared.u64 t, %1; cvt.u32.u64 %0, t; }"
        : "=r"(a) : "l"(p));
    return a;
}
__device__ __forceinline__ void cp16(uint32_t s, const void* g) {
    asm volatile("cp.async.cg.shared.global [%0], [%1], 16;" :: "r"(s), "l"(g));
}
#define CP_COMMIT() asm volatile("cp.async.commit_group;" ::: "memory")
#define CP_WAIT(n)  asm volatile("cp.async.wait_group %0;" :: "n"(n) : "memory")

__device__ __forceinline__ void mma16816(float* c, const uint32_t* a,
                                         const uint32_t* b) {
    asm volatile(
        "mma.sync.aligned.m16n8k16.row.col.f32.bf16.bf16.f32 "
        "{%0,%1,%2,%3}, {%4,%5,%6,%7}, {%8,%9}, {%0,%1,%2,%3};"
        : "+f"(c[0]), "+f"(c[1]), "+f"(c[2]), "+f"(c[3])
        : "r"(a[0]), "r"(a[1]), "r"(a[2]), "r"(a[3]), "r"(b[0]), "r"(b[1]));
}
__device__ __forceinline__ void mma16816h(float* c, const uint32_t* a,
                                          const uint32_t* b) {
    asm volatile(
        "mma.sync.aligned.m16n8k16.row.col.f32.f16.f16.f32 "
        "{%0,%1,%2,%3}, {%4,%5,%6,%7}, {%8,%9}, {%0,%1,%2,%3};"
        : "+f"(c[0]), "+f"(c[1]), "+f"(c[2]), "+f"(c[3])
        : "r"(a[0]), "r"(a[1]), "r"(a[2]), "r"(a[3]), "r"(b[0]), "r"(b[1]));
}
__device__ __forceinline__ void ldmx4(uint32_t* r, uint32_t addr) {
    asm volatile("ldmatrix.sync.aligned.m8n8.x4.shared.b16 {%0,%1,%2,%3}, [%4];"
        : "=r"(r[0]), "=r"(r[1]), "=r"(r[2]), "=r"(r[3]) : "r"(addr));
}
__device__ __forceinline__ void ldmx4t(uint32_t* r, uint32_t addr) {
    asm volatile("ldmatrix.sync.aligned.m8n8.x4.trans.shared.b16 "
                 "{%0,%1,%2,%3}, [%4];"
        : "=r"(r[0]), "=r"(r[1]), "=r"(r[2]), "=r"(r[3]) : "r"(addr));
}
__device__ __forceinline__ uint32_t packbf(float lo_e, float hi_e) {
    uint32_t d;
    asm("cvt.rn.bf16x2.f32 %0, %1, %2;" : "=r"(d) : "f"(hi_e), "f"(lo_e));
    return d;
}
__device__ __forceinline__ float bf16hi(float x) {
    return __bfloat162float(__float2bfloat16_rn(x));
}

// ---------------------------------------------------------------------------
// split: fp32 packed -> (hi, lo) bf16 packed
// ---------------------------------------------------------------------------
__global__ void split_kernel(const float* __restrict__ X,
                             __nv_bfloat16* __restrict__ hi,
                             __nv_bfloat16* __restrict__ lo, int n4)
{
    int i = blockIdx.x * blockDim.x + threadIdx.x;
    if (i >= n4) return;
    float4 x = reinterpret_cast<const float4*>(X)[i];
    __nv_bfloat16 h[4], l[4];
    float xs[4] = {x.x, x.y, x.z, x.w};
    #pragma unroll
    for (int k = 0; k < 4; k++) {
        h[k] = __float2bfloat16_rn(xs[k]);
        l[k] = __float2bfloat16_rn(xs[k] - __bfloat162float(h[k]));
    }
    *reinterpret_cast<uint2*>(hi + 4*(size_t)i) = *reinterpret_cast<uint2*>(h);
    *reinterpret_cast<uint2*>(lo + 4*(size_t)i) = *reinterpret_cast<uint2*>(l);
}

// ---------------------------------------------------------------------------
// strided split (for V slice of fused QKV buffer) -> packed bf16 hi/lo
// ---------------------------------------------------------------------------
__global__ void split_strided_kernel(const float* __restrict__ X,
                                     __nv_bfloat16* __restrict__ hi,
                                     __nv_bfloat16* __restrict__ lo,
                                     int width, int srcstride, int coloff, int n4)
{
    int i = blockIdx.x * blockDim.x + threadIdx.x;
    if (i >= n4) return;
    int e0 = i * 4;
    int row = e0 / width, col = e0 % width;
    const float* src = X + (size_t)row * srcstride + coloff + col;
    float4 x = *reinterpret_cast<const float4*>(src);
    __nv_bfloat16 h[4], l[4];
    float xs[4] = {x.x, x.y, x.z, x.w};
    #pragma unroll
    for (int k = 0; k < 4; k++) {
        h[k] = __float2bfloat16_rn(xs[k]);
        l[k] = __float2bfloat16_rn(xs[k] - __bfloat162float(h[k]));
    }
    *reinterpret_cast<uint2*>(hi + (size_t)e0) = *reinterpret_cast<uint2*>(h);
    *reinterpret_cast<uint2*>(lo + (size_t)e0) = *reinterpret_cast<uint2*>(l);
}

// ---------------------------------------------------------------------------
// rope + split with source row stride / col offset (reads fused QKV buffer)
// ---------------------------------------------------------------------------
__global__ void rope_split_kernel(const float* __restrict__ X,
                                  const float* __restrict__ cosb,
                                  const float* __restrict__ sinb,
                                  __nv_bfloat16* __restrict__ hi,
                                  __nv_bfloat16* __restrict__ lo,
                                  float scale, int nheads,
                                  int rowstride, int coloff)
{
    int idx = blockIdx.x * blockDim.x + threadIdx.x;
    int half = idx & 63;
    int hrow = idx >> 6;
    int rowidx = hrow / nheads;
    int head = hrow - rowidx * nheads;
    int s = rowidx % S;
    const float* src = X + (size_t)rowidx * rowstride + coloff + head * HD;
    size_t dbase = (size_t)hrow * HD;
    float x0 = src[half];
    float x1 = src[half + 64];
    float c0 = cosb[s * 64 + (half >> 1)];
    float s0 = sinb[s * 64 + (half >> 1)];
    float c1 = cosb[s * 64 + ((half + 64) >> 1)];
    float s1 = sinb[s * 64 + ((half + 64) >> 1)];
    float y0 = (x0 * c0 - x1 * s0) * scale;
    float y1 = (x1 * c1 + x0 * s1) * scale;
    float h0 = bf16hi(y0), h1 = bf16hi(y1);
    hi[dbase + half]      = __float2bfloat16_rn(h0);
    hi[dbase + half + 64] = __float2bfloat16_rn(h1);
    lo[dbase + half]      = __float2bfloat16_rn(y0 - h0);
    lo[dbase + half + 64] = __float2bfloat16_rn(y1 - h1);
}

// ---------------------------------------------------------------------------
// transpose + split: W [R, C] fp32 -> T [C, R] bf16 hi/lo (z: up to 2 triples)
// ---------------------------------------------------------------------------
__global__ void transpose_split_kernel(const float* __restrict__ W0,
                                       __nv_bfloat16* __restrict__ Thi0,
                                       __nv_bfloat16* __restrict__ Tlo0,
                                       const float* __restrict__ W1,
                                       __nv_bfloat16* __restrict__ Thi1,
                                       __nv_bfloat16* __restrict__ Tlo1,
                                       int R, int C)
{
    const float* W = blockIdx.z ? W1 : W0;
    __nv_bfloat16* Thi = blockIdx.z ? Thi1 : Thi0;
    __nv_bfloat16* Tlo = blockIdx.z ? Tlo1 : Tlo0;
    __shared__ float t[32][33];
    int c0 = blockIdx.x * 32, r0 = blockIdx.y * 32;
    int tx = threadIdx.x, ty = threadIdx.y;
    #pragma unroll
    for (int i = 0; i < 32; i += 8)
        t[ty + i][tx] = W[(size_t)(r0 + ty + i) * C + c0 + tx];
    __syncthreads();
    #pragma unroll
    for (int i = 0; i < 32; i += 8) {
        float x = t[tx][ty + i];
        size_t o = (size_t)(c0 + ty + i) * R + r0 + tx;
        __nv_bfloat16 h = __float2bfloat16_rn(x);
        Thi[o] = h;
        Tlo[o] = __float2bfloat16_rn(x - __bfloat162float(h));
    }
}

// ---------------------------------------------------------------------------
// transpose + convert: W [R, C] fp32 -> T [C, R] fp16
// ---------------------------------------------------------------------------
__global__ void transpose_convert_kernel(const float* __restrict__ W,
                                         __half* __restrict__ T, int R, int C)
{
    __shared__ float t[32][33];
    int c0 = blockIdx.x * 32, r0 = blockIdx.y * 32;
    int tx = threadIdx.x, ty = threadIdx.y;
    #pragma unroll
    for (int i = 0; i < 32; i += 8)
        t[ty + i][tx] = W[(size_t)(r0 + ty + i) * C + c0 + tx];
    __syncthreads();
    #pragma unroll
    for (int i = 0; i < 32; i += 8)
        T[(size_t)(c0 + ty + i) * R + r0 + tx] = __float2half_rn(t[tx][ty + i]);
}

// ---------------------------------------------------------------------------
// HMMA bf16x3 GEMM: CTA 256x128, 8 warps (4x2), warp tile 64x64, BK=64,
// 2-stage cp.async, ldmatrix fragments. (QKV projection)
// ---------------------------------------------------------------------------
#define ASTR 72
#define STG2 55296                 // bf16 units per stage
#define OFF_ALO 18432
#define OFF_BHI 36864
#define OFF_BLO 46080
#define GEMM_SMEM (2*STG2*2)       // 221184 bytes

__global__ __launch_bounds__(256, 1)
void gemm_bf16x3_kernel(float* __restrict__ C,
    const __nv_bfloat16* __restrict__ Ahi, const __nv_bfloat16* __restrict__ Alo,
    const __nv_bfloat16* __restrict__ Bhi, const __nv_bfloat16* __restrict__ Blo,
    int M, int N, int K)
{
    extern __shared__ __nv_bfloat16 smb[];
    const uint32_t smem_base = smem_u32(smb);
    const int tid = threadIdx.x;
    const int wid = tid >> 5, lane = tid & 31;
    const int g = lane >> 2, tig = lane & 3;
    const int wm = wid >> 1, wn = wid & 1;          // 4 x 2 warp grid
    const int m0 = blockIdx.y * 256, n0 = blockIdx.x * 128;
    const int nch = K >> 6;

    const int rowselA = ((lane >> 3) & 1) * 8 + (lane & 7);
    const int colselA = ((lane >> 4) & 1) * 8;
    const int bcolsel = ((lane >> 4) & 1) * 8 + (lane & 7);
    const int bksel   = ((lane >> 3) & 1) * 8;

    auto load_chunk = [&](int c, int stage) {
        const int k0 = c << 6;
        const uint32_t sb = smem_base + (uint32_t)(stage * STG2) * 2;
        #pragma unroll
        for (int i = 0; i < 8; ++i) {
            int v = i * 256 + tid; int r = v >> 3, ch = v & 7;
            cp16(sb + (uint32_t)(r * ASTR + ch * 8) * 2,
                 Ahi + (size_t)(m0 + r) * K + k0 + ch * 8);
        }
        #pragma unroll
        for (int i = 0; i < 8; ++i) {
            int v = i * 256 + tid; int r = v >> 3, ch = v & 7;
            cp16(sb + (uint32_t)(OFF_ALO + r * ASTR + ch * 8) * 2,
                 Alo + (size_t)(m0 + r) * K + k0 + ch * 8);
        }
        #pragma unroll
        for (int i = 0; i < 4; ++i) {
            int v = i * 256 + tid; int r = v >> 3, ch = v & 7;
            cp16(sb + (uint32_t)(OFF_BHI + r * ASTR + ch * 8) * 2,
                 Bhi + (size_t)(n0 + r) * K + k0 + ch * 8);
            cp16(sb + (uint32_t)(OFF_BLO + r * ASTR + ch * 8) * 2,
                 Blo + (size_t)(n0 + r) * K + k0 + ch * 8);
        }
    };

    float acc[4][8][4];
    #pragma unroll
    for (int mi = 0; mi < 4; mi++)
        #pragma unroll
        for (int ni = 0; ni < 8; ni++)
            #pragma unroll
            for (int r = 0; r < 4; r++) acc[mi][ni][r] = 0.f;

    load_chunk(0, 0);
    CP_COMMIT();

    for (int c = 0; c < nch; ++c) {
        if (c + 1 < nch) { load_chunk(c + 1, (c + 1) & 1); CP_COMMIT(); CP_WAIT(1); }
        else             { CP_WAIT(0); }
        __syncthreads();

        const uint32_t stg = smem_base + (uint32_t)((c & 1) * STG2) * 2;
        const uint32_t bAh = stg;
        const uint32_t bAl = stg + (uint32_t)OFF_ALO * 2;
        const uint32_t bBh = stg + (uint32_t)OFF_BHI * 2;
        const uint32_t bBl = stg + (uint32_t)OFF_BLO * 2;

        #pragma unroll
        for (int ks = 0; ks < 4; ++ks) {
            const int kk0 = ks * 16;
            uint32_t Ah[4][4], Al[4][4], Bh[4][4], Bl[4][4];
            #pragma unroll
            for (int mi = 0; mi < 4; ++mi) {
                uint32_t ar = (uint32_t)((wm * 64 + mi * 16 + rowselA) * ASTR
                                         + kk0 + colselA) * 2;
                ldmx4(Ah[mi], bAh + ar);
                ldmx4(Al[mi], bAl + ar);
            }
            #pragma unroll
            for (int nip = 0; nip < 4; ++nip) {
                uint32_t br = (uint32_t)((wn * 64 + nip * 16 + bcolsel) * ASTR
                                         + kk0 + bksel) * 2;
                ldmx4(Bh[nip], bBh + br);
                ldmx4(Bl[nip], bBl + br);
            }
            #pragma unroll
            for (int mi = 0; mi < 4; ++mi)
                #pragma unroll
                for (int ni = 0; ni < 8; ++ni) {
                    const uint32_t* bh = &Bh[ni >> 1][(ni & 1) * 2];
                    const uint32_t* bl = &Bl[ni >> 1][(ni & 1) * 2];
                    mma16816(acc[mi][ni], Ah[mi], bh);
                    mma16816(acc[mi][ni], Ah[mi], bl);
                    mma16816(acc[mi][ni], Al[mi], bh);
                }
        }
        __syncthreads();
    }

    #pragma unroll
    for (int mi = 0; mi < 4; ++mi) {
        int rm = m0 + wm * 64 + mi * 16 + g;
        #pragma unroll
        for (int ni = 0; ni < 8; ++ni) {
            int cn = n0 + wn * 64 + ni * 8 + 2 * tig;
            *(float2*)(C + (size_t)rm * N + cn) =
                make_float2(acc[mi][ni][0], acc[mi][ni][1]);
            *(float2*)(C + (size_t)(rm + 8) * N + cn) =
                make_float2(acc[mi][ni][2], acc[mi][ni][3]);
        }
    }
}

// ---------------------------------------------------------------------------
// fp16 single-pass GEMM (output projection): CTA 256x128, warp 64x64, BK=64.
// Error ~4e-4 rel (fp16 half-ulp rounding of both operands) — linear path,
// no softmax amplification.
// ---------------------------------------------------------------------------
#define FOFF_B (256*ASTR)
#define FSTG (384*ASTR)            // halfs per stage = 27648
#define GEMMH_SMEM (2*FSTG*2)      // 110592 bytes

__global__ __launch_bounds__(256, 1)
void gemm_f16_kernel(float* __restrict__ C,
    const __half* __restrict__ A, const __half* __restrict__ Bm,
    int M, int N, int K)
{
    extern __shared__ __half smh[];
    const uint32_t smem_base = smem_u32(smh);
    const int tid = threadIdx.x;
    const int wid = tid >> 5, lane = tid & 31;
    const int g = lane >> 2, tig = lane & 3;
    const int wm = wid >> 1, wn = wid & 1;
    const int m0 = blockIdx.y * 256, n0 = blockIdx.x * 128;
    const int nch = K >> 6;

    const int rowselA = ((lane >> 3) & 1) * 8 + (lane & 7);
    const int colselA = ((lane >> 4) & 1) * 8;
    const int bcolsel = ((lane >> 4) & 1) * 8 + (lane & 7);
    const int bksel   = ((lane >> 3) & 1) * 8;

    auto load_chunk = [&](int c, int stage) {
        const int k0 = c << 6;
        const uint32_t sb = smem_base + (uint32_t)(stage * FSTG) * 2;
        #pragma unroll
        for (int i = 0; i < 8; ++i) {
            int v = i * 256 + tid; int r = v >> 3, ch = v & 7;
            cp16(sb + (uint32_t)(r * ASTR + ch * 8) * 2,
                 A + (size_t)(m0 + r) * K + k0 + ch * 8);
        }
        #pragma unroll
        for (int i = 0; i < 4; ++i) {
            int v = i * 256 + tid; int r = v >> 3, ch = v & 7;
            cp16(sb + (uint32_t)(FOFF_B + r * ASTR + ch * 8) * 2,
                 Bm + (size_t)(n0 + r) * K + k0 + ch * 8);
        }
    };

    float acc[4][8][4];
    #pragma unroll
    for (int mi = 0; mi < 4; mi++)
        #pragma unroll
        for (int ni = 0; ni < 8; ni++)
            #pragma unroll
            for (int r = 0; r < 4; r++) acc[mi][ni][r] = 0.f;

    load_chunk(0, 0);
    CP_COMMIT();

    for (int c = 0; c < nch; ++c) {
        if (c + 1 < nch) { load_chunk(c + 1, (c + 1) & 1); CP_COMMIT(); CP_WAIT(1); }
        else             { CP_WAIT(0); }
        __syncthreads();

        const uint32_t stg = smem_base + (uint32_t)((c & 1) * FSTG) * 2;
        const uint32_t bA = stg;
        const uint32_t bB = stg + (uint32_t)FOFF_B * 2;

        #pragma unroll
        for (int ks = 0; ks < 4; ++ks) {
            const int kk0 = ks * 16;
            uint32_t Ah[4][4], Bh[4][4];
            #pragma unroll
            for (int mi = 0; mi < 4; ++mi) {
                uint32_t ar = (uint32_t)((wm * 64 + mi * 16 + rowselA) * ASTR
                                         + kk0 + colselA) * 2;
                ldmx4(Ah[mi], bA + ar);
            }
            #pragma unroll
            for (int nip = 0; nip < 4; ++nip) {
                uint32_t br = (uint32_t)((wn * 64 + nip * 16 + bcolsel) * ASTR
                                         + kk0 + bksel) * 2;
                ldmx4(Bh[nip], bB + br);
            }
            #pragma unroll
            for (int mi = 0; mi < 4; ++mi)
                #pragma unroll
                for (int ni = 0; ni < 8; ++ni)
                    mma16816h(acc[mi][ni], Ah[mi], &Bh[ni >> 1][(ni & 1) * 2]);
        }
        __syncthreads();
    }

    #pragma unroll
    for (int mi = 0; mi < 4; ++mi) {
        int rm = m0 + wm * 64 + mi * 16 + g;
        #pragma unroll
        for (int ni = 0; ni < 8; ++ni) {
            int cn = n0 + wn * 64 + ni * 8 + 2 * tig;
            *(float2*)(C + (size_t)rm * N + cn) =
                make_float2(acc[mi][ni][0], acc[mi][ni][1]);
            *(float2*)(C + (size_t)(rm + 8) * N + cn) =
                make_float2(acc[mi][ni][2], acc[mi][ni][3]);
        }
    }
}

// ---------------------------------------------------------------------------
// FA2-style HMMA flash attention; writes fp16 O directly.
// ---------------------------------------------------------------------------
#define QSF 136
#define STG_KV (4*64*QSF*2)
#define OFF_KV 69632
#define FLASH_SMEM (OFF_KV + 2*STG_KV)   // 208896 bytes

__global__ __launch_bounds__(256, 1) void flash_hmma_kernel(
    const __nv_bfloat16* __restrict__ Qhi, const __nv_bfloat16* __restrict__ Qlo,
    const __nv_bfloat16* __restrict__ Khi, const __nv_bfloat16* __restrict__ Klo,
    const __nv_bfloat16* __restrict__ Vhi, const __nv_bfloat16* __restrict__ Vlo,
    __half* __restrict__ O16)
{
    const int m_tile = gridDim.x - 1 - blockIdx.x;   // heavy CTAs first
    const int h = blockIdx.y;
    const int b = blockIdx.z;
    const int kvh = h / GROUPS;
    const int tid = threadIdx.x;
    const int warp = tid >> 5, lane = tid & 31;
    const int g = lane >> 2, tig = lane & 3;
    const int m0 = m_tile * 128;
    const int wrow = warp * 16;

    extern __shared__ char smc[];
    const uint32_t base = smem_u32(smc);

    const int rowselA = ((lane >> 3) & 1) * 8 + (lane & 7);
    const int colselA = ((lane >> 4) & 1) * 8;
    const int bcolsel = ((lane >> 4) & 1) * 8 + (lane & 7);
    const int bksel   = ((lane >> 3) & 1) * 8;
    const uint32_t voff = (uint32_t)(((lane & 7) + ((lane >> 3) & 1) * 8) * QSF
                                     + (lane >> 4) * 8);

    const __nv_bfloat16* kvsrc[4] = {Khi, Klo, Vhi, Vlo};
    auto load_kv = [&](int nt, int stage) {
        const int n0 = nt * 64;
        const uint32_t sb = base + OFF_KV + (uint32_t)stage * STG_KV;
        #pragma unroll
        for (int i = 0; i < 16; ++i) {
            int v = i * 256 + tid;
            int mat = v >> 10;
            int r = (v >> 4) & 63;
            int ch = v & 15;
            const __nv_bfloat16* src = kvsrc[mat]
                + (((size_t)b * S + n0 + r) * KVH + kvh) * HD + ch * 8;
            cp16(sb + (uint32_t)(mat * (64 * QSF) + r * QSF + ch * 8) * 2, src);
        }
    };

    #pragma unroll
    for (int i = 0; i < 16; ++i) {
        int v = i * 256 + tid;
        int mat = v >> 11;
        int r = (v >> 4) & 127;
        int ch = v & 15;
        const __nv_bfloat16* src = (mat ? Qlo : Qhi)
            + (((size_t)b * S + m0 + r) * H + h) * HD + ch * 8;
        cp16(base + (uint32_t)(mat * (128 * QSF) + r * QSF + ch * 8) * 2, src);
    }
    load_kv(0, 0);
    CP_COMMIT();

    float acc[16][4];
    #pragma unroll
    for (int ni = 0; ni < 16; ++ni)
        #pragma unroll
        for (int r = 0; r < 4; ++r) acc[ni][r] = 0.f;

    float m_run0 = -1e30f, m_run1 = -1e30f;
    float l_run0 = 0.f, l_run1 = 0.f;

    const int ntmax = 2 * m_tile + 1;
    for (int nt = 0; nt <= ntmax; ++nt) {
        const int n0 = nt * 64;
        if (nt < ntmax) { load_kv(nt + 1, (nt + 1) & 1); CP_COMMIT(); CP_WAIT(1); }
        else            { CP_WAIT(0); }
        __syncthreads();

        const uint32_t kvb = base + OFF_KV + (uint32_t)(nt & 1) * STG_KV;
        const uint32_t bKh = kvb;
        const uint32_t bKl = kvb + (uint32_t)(64 * QSF) * 2;
        const uint32_t bVh = kvb + (uint32_t)(2 * 64 * QSF) * 2;
        const uint32_t bVl = kvb + (uint32_t)(3 * 64 * QSF) * 2;

        float cs[8][4];
        #pragma unroll
        for (int ni = 0; ni < 8; ++ni)
            #pragma unroll
            for (int r = 0; r < 4; ++r) cs[ni][r] = 0.f;

        #pragma unroll
        for (int ks = 0; ks < 8; ++ks) {
            const int kk0 = ks * 16;
            uint32_t qh[4], ql[4];
            uint32_t ar = (uint32_t)((wrow + rowselA) * QSF + kk0 + colselA) * 2;
            ldmx4(qh, base + ar);
            ldmx4(ql, base + (uint32_t)(128 * QSF) * 2 + ar);
            #pragma unroll
            for (int nip = 0; nip < 4; ++nip) {
                uint32_t kh[4], kl[4];
                uint32_t br = (uint32_t)((nip * 16 + bcolsel) * QSF + kk0 + bksel) * 2;
                ldmx4(kh, bKh + br);
                ldmx4(kl, bKl + br);
                mma16816(cs[2 * nip],     qh, kh);
                mma16816(cs[2 * nip],     qh, kl);
                mma16816(cs[2 * nip],     ql, kh);
                mma16816(cs[2 * nip + 1], qh, kh + 2);
                mma16816(cs[2 * nip + 1], qh, kl + 2);
                mma16816(cs[2 * nip + 1], ql, kh + 2);
            }
        }

        const int r0g = m0 + wrow + g;
        const int colb = n0 + 2 * tig;
        #pragma unroll
        for (int ni = 0; ni < 8; ++ni) {
            int c = colb + ni * 8;
            if (c > r0g)         cs[ni][0] = -1e30f;
            if (c + 1 > r0g)     cs[ni][1] = -1e30f;
            if (c > r0g + 8)     cs[ni][2] = -1e30f;
            if (c + 1 > r0g + 8) cs[ni][3] = -1e30f;
        }

        float mx0 = -1e30f, mx1 = -1e30f;
        #pragma unroll
        for (int ni = 0; ni < 8; ++ni) {
            mx0 = fmaxf(mx0, fmaxf(cs[ni][0], cs[ni][1]));
            mx1 = fmaxf(mx1, fmaxf(cs[ni][2], cs[ni][3]));
        }
        mx0 = fmaxf(mx0, __shfl_xor_sync(0xFFFFFFFFu, mx0, 1));
        mx0 = fmaxf(mx0, __shfl_xor_sync(0xFFFFFFFFu, mx0, 2));
        mx1 = fmaxf(mx1, __shfl_xor_sync(0xFFFFFFFFu, mx1, 1));
        mx1 = fmaxf(mx1, __shfl_xor_sync(0xFFFFFFFFu, mx1, 2));
        const float mn0 = fmaxf(m_run0, mx0);
        const float mn1 = fmaxf(m_run1, mx1);
        const float corr0 = __expf(m_run0 - mn0);
        const float corr1 = __expf(m_run1 - mn1);
        float sum0 = 0.f, sum1 = 0.f;
        #pragma unroll
        for (int ni = 0; ni < 8; ++ni) {
            cs[ni][0] = __expf(cs[ni][0] - mn0); sum0 += cs[ni][0];
            cs[ni][1] = __expf(cs[ni][1] - mn0); sum0 += cs[ni][1];
            cs[ni][2] = __expf(cs[ni][2] - mn1); sum1 += cs[ni][2];
            cs[ni][3] = __expf(cs[ni][3] - mn1); sum1 += cs[ni][3];
        }
        sum0 += __shfl_xor_sync(0xFFFFFFFFu, sum0, 1);
        sum0 += __shfl_xor_sync(0xFFFFFFFFu, sum0, 2);
        sum1 += __shfl_xor_sync(0xFFFFFFFFu, sum1, 1);
        sum1 += __shfl_xor_sync(0xFFFFFFFFu, sum1, 2);
        l_run0 = l_run0 * corr0 + sum0;
        l_run1 = l_run1 * corr1 + sum1;
        m_run0 = mn0;
        m_run1 = mn1;
        #pragma unroll
        for (int ni = 0; ni < 16; ++ni) {
            acc[ni][0] *= corr0; acc[ni][1] *= corr0;
            acc[ni][2] *= corr1; acc[ni][3] *= corr1;
        }

        #pragma unroll
        for (int kp = 0; kp < 4; ++kp) {
            uint32_t aph[4], apl[4];
            #pragma unroll
            for (int t = 0; t < 4; ++t) {
                int nn = 2 * kp + (t >> 1);
                int j0 = (t & 1) * 2;
                float p0 = cs[nn][j0], p1 = cs[nn][j0 + 1];
                float h0 = bf16hi(p0), h1 = bf16hi(p1);
                aph[t] = packbf(h0, h1);
                apl[t] = packbf(p0 - h0, p1 - h1);
            }
            #pragma unroll
            for (int np = 0; np < 8; ++np) {
                uint32_t bh[4], bl[4];
                uint32_t va = (uint32_t)(voff + kp * 16 * QSF + np * 16) * 2;
                ldmx4t(bh, bVh + va);
                ldmx4t(bl, bVl + va);
                mma16816(acc[2 * np],     aph, bh);
                mma16816(acc[2 * np],     aph, bl);
                mma16816(acc[2 * np],     apl, bh);
                mma16816(acc[2 * np + 1], aph, bh + 2);
                mma16816(acc[2 * np + 1], aph, bl + 2);
                mma16816(acc[2 * np + 1], apl, bh + 2);
            }
        }
        __syncthreads();
    }

    const float inv0 = 1.f / l_run0;
    const float inv1 = 1.f / l_run1;
    const size_t row0 = (size_t)b * S + m0 + wrow + g;
    __half* o0 = O16 + row0 * (H * HD) + h * HD;
    __half* o1 = o0 + 8 * (size_t)(H * HD);
    #pragma unroll
    for (int ni = 0; ni < 16; ++ni) {
        int c = ni * 8 + 2 * tig;
        __half2 p0 = __floats2half2_rn(acc[ni][0] * inv0, acc[ni][1] * inv0);
        __half2 p1 = __floats2half2_rn(acc[ni][2] * inv1, acc[ni][3] * inv1);
        *(__half2*)(o0 + c) = p0;
        *(__half2*)(o1 + c) = p1;
    }
}

// ---------------------------------------------------------------------------
extern "C" void kernel_launch(void* const* d_in, const int* in_sizes, int n_in,
                              void* d_out, int out_size)
{
    const float* x    = (const float*)d_in[0];
    const float* cosb = (const float*)d_in[1];
    const float* sinb = (const float*)d_in[2];
    const float* Wq   = (const float*)d_in[4];
    const float* Wk   = (const float*)d_in[5];
    const float* Wv   = (const float*)d_in[6];
    const float* Wo   = (const float*)d_in[7];
    float* out = (float*)d_out;

    float* QKVp;
    cudaGetSymbolAddress((void**)&QKVp, g_QKV);
    __nv_bfloat16 *xhi, *xlo, *wqkvh, *wqkvl;
    __nv_bfloat16 *qhi, *qlo, *khi, *klo, *vhi, *vlo;
    __half *wo16, *o16;
    cudaGetSymbolAddress((void**)&xhi, g_xhi);
    cudaGetSymbolAddress((void**)&xlo, g_xlo);
    cudaGetSymbolAddress((void**)&wqkvh, g_WqkvT_hi);
    cudaGetSymbolAddress((void**)&wqkvl, g_WqkvT_lo);
    cudaGetSymbolAddress((void**)&wo16, g_Wo16T);
    cudaGetSymbolAddress((void**)&o16, g_O16);
    cudaGetSymbolAddress((void**)&qhi, g_Qhi);
    cudaGetSymbolAddress((void**)&qlo, g_Qlo);
    cudaGetSymbolAddress((void**)&khi, g_Khi);
    cudaGetSymbolAddress((void**)&klo, g_Klo);
    cudaGetSymbolAddress((void**)&vhi, g_Vhi);
    cudaGetSymbolAddress((void**)&vlo, g_Vlo);

    const int M = M_ROWS;  // 4096

    // prep
    split_kernel<<<(M * D / 4) / 256, 256>>>(x, xhi, xlo, M * D / 4);
    transpose_split_kernel<<<dim3(D / 32, D / 32), dim3(32, 8)>>>(
        Wq, wqkvh, wqkvl, nullptr, nullptr, nullptr, D, H * HD);
    transpose_split_kernel<<<dim3((KVH * HD) / 32, D / 32, 2), dim3(32, 8)>>>(
        Wk, wqkvh + (size_t)(H * HD) * D, wqkvl + (size_t)(H * HD) * D,
        Wv, wqkvh + (size_t)(H * HD + KVH * HD) * D,
            wqkvl + (size_t)(H * HD + KVH * HD) * D, D, KVH * HD);
    transpose_convert_kernel<<<dim3(D / 32, (H * HD) / 32), dim3(32, 8)>>>(
        Wo, wo16, H * HD, D);

    cudaFuncSetAttribute(gemm_bf16x3_kernel,
                         cudaFuncAttributeMaxDynamicSharedMemorySize, GEMM_SMEM);
    cudaFuncSetAttribute(gemm_f16_kernel,
                         cudaFuncAttributeMaxDynamicSharedMemorySize, GEMMH_SMEM);

    // fused QKV projection: [4096, 3072] (bf16x3, precision-critical path)
    gemm_bf16x3_kernel<<<dim3(NQKV / 128, M / 256), 256, GEMM_SMEM>>>(
        QKVp, xhi, xlo, wqkvh, wqkvl, M, NQKV, D);

    // rope + split from fused buffer (Q scaled); V strided split
    rope_split_kernel<<<(B * S * H * 64) / 256, 256>>>(
        QKVp, cosb, sinb, qhi, qlo, SCALE, H, NQKV, 0);
    rope_split_kernel<<<(B * S * KVH * 64) / 256, 256>>>(
        QKVp, cosb, sinb, khi, klo, 1.0f, KVH, NQKV, H * HD);
    split_strided_kernel<<<(M * KVH * HD / 4) / 256, 256>>>(
        QKVp, vhi, vlo, KVH * HD, NQKV, H * HD + KVH * HD, M * KVH * HD / 4);

    // flash attention -> fp16 O
    cudaFuncSetAttribute(flash_hmma_kernel,
                         cudaFuncAttributeMaxDynamicSharedMemorySize, FLASH_SMEM);
    flash_hmma_kernel<<<dim3(S / 128, H, B), 256, FLASH_SMEM>>>(
        qhi, qlo, khi, klo, vhi, vlo, o16);

    // output projection: fp16 single-pass (linear error path)
    gemm_f16_kernel<<<dim3(D / 128, M / 256), 256, GEMMH_SMEM>>>(
        out, o16, wo16, M, D, D);
}

// round 13
// speedup vs baseline: 1.5208x; 1.1953x over previous
#include <cuda_runtime.h>
#include <cuda_bf16.h>
#include <cuda_fp16.h>
#include <math.h>
#include <stdint.h>

#define B 2
#define S 2048
#define D 2048
#define H 16
#define KVH 4
#define HD 128
#define GROUPS (H/KVH)
#define SCALE 0.08838834764831845f
#define M_ROWS (B*S)          // 4096
#define NQKV (H*HD + 2*KVH*HD)   // 3072

// ---------------- scratch (__device__ globals; no allocation) --------------
__device__ float g_QKV[M_ROWS*NQKV];           // fused projection output

__device__ __nv_bfloat16 g_xhi[M_ROWS*D],  g_xlo[M_ROWS*D];
__device__ __nv_bfloat16 g_WqkvT_hi[NQKV*D], g_WqkvT_lo[NQKV*D];  // [3072,2048]
__device__ __half g_Wo16T[D*H*HD];             // [2048,2048] fp16
__device__ __half g_O16[M_ROWS*D];             // flash output, fp16

__device__ __half g_Q16[B*S*H*HD];
__device__ __half g_K16[B*S*KVH*HD];
__device__ __half g_V16[B*S*KVH*HD];

// ---------------------------- helpers --------------------------------------
__device__ __forceinline__ uint32_t smem_u32(const void* p) {
    uint32_t a;
    asm("{ .reg .u64 t; cvta.to.shared.u64 t, %1; cvt.u32.u64 %0, t; }"
        : "=r"(a) : "l"(p));
    return a;
}
__device__ __forceinline__ void cp16(uint32_t s, const void* g) {
    asm volatile("cp.async.cg.shared.global [%0], [%1], 16;" :: "r"(s), "l"(g));
}
#define CP_COMMIT() asm volatile("cp.async.commit_group;" ::: "memory")
#define CP_WAIT(n)  asm volatile("cp.async.wait_group %0;" :: "n"(n) : "memory")

__device__ __forceinline__ void mma16816(float* c, const uint32_t* a,
                                         const uint32_t* b) {
    asm volatile(
        "mma.sync.aligned.m16n8k16.row.col.f32.bf16.bf16.f32 "
        "{%0,%1,%2,%3}, {%4,%5,%6,%7}, {%8,%9}, {%0,%1,%2,%3};"
        : "+f"(c[0]), "+f"(c[1]), "+f"(c[2]), "+f"(c[3])
        : "r"(a[0]), "r"(a[1]), "r"(a[2]), "r"(a[3]), "r"(b[0]), "r"(b[1]));
}
__device__ __forceinline__ void mma16816h(float* c, const uint32_t* a,
                                          const uint32_t* b) {
    asm volatile(
        "mma.sync.aligned.m16n8k16.row.col.f32.f16.f16.f32 "
        "{%0,%1,%2,%3}, {%4,%5,%6,%7}, {%8,%9}, {%0,%1,%2,%3};"
        : "+f"(c[0]), "+f"(c[1]), "+f"(c[2]), "+f"(c[3])
        : "r"(a[0]), "r"(a[1]), "r"(a[2]), "r"(a[3]), "r"(b[0]), "r"(b[1]));
}
__device__ __forceinline__ void ldmx4(uint32_t* r, uint32_t addr) {
    asm volatile("ldmatrix.sync.aligned.m8n8.x4.shared.b16 {%0,%1,%2,%3}, [%4];"
        : "=r"(r[0]), "=r"(r[1]), "=r"(r[2]), "=r"(r[3]) : "r"(addr));
}
__device__ __forceinline__ void ldmx4t(uint32_t* r, uint32_t addr) {
    asm volatile("ldmatrix.sync.aligned.m8n8.x4.trans.shared.b16 "
                 "{%0,%1,%2,%3}, [%4];"
        : "=r"(r[0]), "=r"(r[1]), "=r"(r[2]), "=r"(r[3]) : "r"(addr));
}
__device__ __forceinline__ float bf16hi(float x) {
    return __bfloat162float(__float2bfloat16_rn(x));
}

// ---------------------------------------------------------------------------
// split: fp32 packed -> (hi, lo) bf16 packed
// ---------------------------------------------------------------------------
__global__ void split_kernel(const float* __restrict__ X,
                             __nv_bfloat16* __restrict__ hi,
                             __nv_bfloat16* __restrict__ lo, int n4)
{
    int i = blockIdx.x * blockDim.x + threadIdx.x;
    if (i >= n4) return;
    float4 x = reinterpret_cast<const float4*>(X)[i];
    __nv_bfloat16 h[4], l[4];
    float xs[4] = {x.x, x.y, x.z, x.w};
    #pragma unroll
    for (int k = 0; k < 4; k++) {
        h[k] = __float2bfloat16_rn(xs[k]);
        l[k] = __float2bfloat16_rn(xs[k] - __bfloat162float(h[k]));
    }
    *reinterpret_cast<uint2*>(hi + 4*(size_t)i) = *reinterpret_cast<uint2*>(h);
    *reinterpret_cast<uint2*>(lo + 4*(size_t)i) = *reinterpret_cast<uint2*>(l);
}

// ---------------------------------------------------------------------------
// strided convert: fp32 (strided rows) -> packed fp16 (for V slice)
// ---------------------------------------------------------------------------
__global__ void convert_strided_kernel(const float* __restrict__ X,
                                       __half* __restrict__ out,
                                       int width, int srcstride, int coloff, int n4)
{
    int i = blockIdx.x * blockDim.x + threadIdx.x;
    if (i >= n4) return;
    int e0 = i * 4;
    int row = e0 / width, col = e0 % width;
    const float* src = X + (size_t)row * srcstride + coloff + col;
    float4 x = *reinterpret_cast<const float4*>(src);
    __half2 h0 = __floats2half2_rn(x.x, x.y);
    __half2 h1 = __floats2half2_rn(x.z, x.w);
    *reinterpret_cast<__half2*>(out + (size_t)e0) = h0;
    *reinterpret_cast<__half2*>(out + (size_t)e0 + 2) = h1;
}

// ---------------------------------------------------------------------------
// rope + convert to fp16 (+ optional scale), reading fused QKV buffer
// ---------------------------------------------------------------------------
__global__ void rope_f16_kernel(const float* __restrict__ X,
                                const float* __restrict__ cosb,
                                const float* __restrict__ sinb,
                                __half* __restrict__ out,
                                float scale, int nheads,
                                int rowstride, int coloff)
{
    int idx = blockIdx.x * blockDim.x + threadIdx.x;
    int half = idx & 63;
    int hrow = idx >> 6;
    int rowidx = hrow / nheads;
    int head = hrow - rowidx * nheads;
    int s = rowidx % S;
    const float* src = X + (size_t)rowidx * rowstride + coloff + head * HD;
    size_t dbase = (size_t)hrow * HD;
    float x0 = src[half];
    float x1 = src[half + 64];
    float c0 = cosb[s * 64 + (half >> 1)];
    float s0 = sinb[s * 64 + (half >> 1)];
    float c1 = cosb[s * 64 + ((half + 64) >> 1)];
    float s1 = sinb[s * 64 + ((half + 64) >> 1)];
    out[dbase + half]      = __float2half_rn((x0 * c0 - x1 * s0) * scale);
    out[dbase + half + 64] = __float2half_rn((x1 * c1 + x0 * s1) * scale);
}

// ---------------------------------------------------------------------------
// transpose + split: W [R, C] fp32 -> T [C, R] bf16 hi/lo (z: up to 2 triples)
// ---------------------------------------------------------------------------
__global__ void transpose_split_kernel(const float* __restrict__ W0,
                                       __nv_bfloat16* __restrict__ Thi0,
                                       __nv_bfloat16* __restrict__ Tlo0,
                                       const float* __restrict__ W1,
                                       __nv_bfloat16* __restrict__ Thi1,
                                       __nv_bfloat16* __restrict__ Tlo1,
                                       int R, int C)
{
    const float* W = blockIdx.z ? W1 : W0;
    __nv_bfloat16* Thi = blockIdx.z ? Thi1 : Thi0;
    __nv_bfloat16* Tlo = blockIdx.z ? Tlo1 : Tlo0;
    __shared__ float t[32][33];
    int c0 = blockIdx.x * 32, r0 = blockIdx.y * 32;
    int tx = threadIdx.x, ty = threadIdx.y;
    #pragma unroll
    for (int i = 0; i < 32; i += 8)
        t[ty + i][tx] = W[(size_t)(r0 + ty + i) * C + c0 + tx];
    __syncthreads();
    #pragma unroll
    for (int i = 0; i < 32; i += 8) {
        float x = t[tx][ty + i];
        size_t o = (size_t)(c0 + ty + i) * R + r0 + tx;
        __nv_bfloat16 h = __float2bfloat16_rn(x);
        Thi[o] = h;
        Tlo[o] = __float2bfloat16_rn(x - __bfloat162float(h));
    }
}

// ---------------------------------------------------------------------------
// transpose + convert: W [R, C] fp32 -> T [C, R] fp16
// ---------------------------------------------------------------------------
__global__ void transpose_convert_kernel(const float* __restrict__ W,
                                         __half* __restrict__ T, int R, int C)
{
    __shared__ float t[32][33];
    int c0 = blockIdx.x * 32, r0 = blockIdx.y * 32;
    int tx = threadIdx.x, ty = threadIdx.y;
    #pragma unroll
    for (int i = 0; i < 32; i += 8)
        t[ty + i][tx] = W[(size_t)(r0 + ty + i) * C + c0 + tx];
    __syncthreads();
    #pragma unroll
    for (int i = 0; i < 32; i += 8)
        T[(size_t)(c0 + ty + i) * R + r0 + tx] = __float2half_rn(t[tx][ty + i]);
}

// ---------------------------------------------------------------------------
// HMMA bf16x3 GEMM: CTA 256x128, 8 warps (4x2), warp tile 64x64, BK=64,
// 2-stage cp.async, ldmatrix fragments. (QKV projection — precision-critical)
// ---------------------------------------------------------------------------
#define ASTR 72
#define STG2 55296                 // bf16 units per stage
#define OFF_ALO 18432
#define OFF_BHI 36864
#define OFF_BLO 46080
#define GEMM_SMEM (2*STG2*2)       // 221184 bytes

__global__ __launch_bounds__(256, 1)
void gemm_bf16x3_kernel(float* __restrict__ C,
    const __nv_bfloat16* __restrict__ Ahi, const __nv_bfloat16* __restrict__ Alo,
    const __nv_bfloat16* __restrict__ Bhi, const __nv_bfloat16* __restrict__ Blo,
    int M, int N, int K)
{
    extern __shared__ __nv_bfloat16 smb[];
    const uint32_t smem_base = smem_u32(smb);
    const int tid = threadIdx.x;
    const int wid = tid >> 5, lane = tid & 31;
    const int g = lane >> 2, tig = lane & 3;
    const int wm = wid >> 1, wn = wid & 1;          // 4 x 2 warp grid
    const int m0 = blockIdx.y * 256, n0 = blockIdx.x * 128;
    const int nch = K >> 6;

    const int rowselA = ((lane >> 3) & 1) * 8 + (lane & 7);
    const int colselA = ((lane >> 4) & 1) * 8;
    const int bcolsel = ((lane >> 4) & 1) * 8 + (lane & 7);
    const int bksel   = ((lane >> 3) & 1) * 8;

    auto load_chunk = [&](int c, int stage) {
        const int k0 = c << 6;
        const uint32_t sb = smem_base + (uint32_t)(stage * STG2) * 2;
        #pragma unroll
        for (int i = 0; i < 8; ++i) {
            int v = i * 256 + tid; int r = v >> 3, ch = v & 7;
            cp16(sb + (uint32_t)(r * ASTR + ch * 8) * 2,
                 Ahi + (size_t)(m0 + r) * K + k0 + ch * 8);
        }
        #pragma unroll
        for (int i = 0; i < 8; ++i) {
            int v = i * 256 + tid; int r = v >> 3, ch = v & 7;
            cp16(sb + (uint32_t)(OFF_ALO + r * ASTR + ch * 8) * 2,
                 Alo + (size_t)(m0 + r) * K + k0 + ch * 8);
        }
        #pragma unroll
        for (int i = 0; i < 4; ++i) {
            int v = i * 256 + tid; int r = v >> 3, ch = v & 7;
            cp16(sb + (uint32_t)(OFF_BHI + r * ASTR + ch * 8) * 2,
                 Bhi + (size_t)(n0 + r) * K + k0 + ch * 8);
            cp16(sb + (uint32_t)(OFF_BLO + r * ASTR + ch * 8) * 2,
                 Blo + (size_t)(n0 + r) * K + k0 + ch * 8);
        }
    };

    float acc[4][8][4];
    #pragma unroll
    for (int mi = 0; mi < 4; mi++)
        #pragma unroll
        for (int ni = 0; ni < 8; ni++)
            #pragma unroll
            for (int r = 0; r < 4; r++) acc[mi][ni][r] = 0.f;

    load_chunk(0, 0);
    CP_COMMIT();

    for (int c = 0; c < nch; ++c) {
        if (c + 1 < nch) { load_chunk(c + 1, (c + 1) & 1); CP_COMMIT(); CP_WAIT(1); }
        else             { CP_WAIT(0); }
        __syncthreads();

        const uint32_t stg = smem_base + (uint32_t)((c & 1) * STG2) * 2;
        const uint32_t bAh = stg;
        const uint32_t bAl = stg + (uint32_t)OFF_ALO * 2;
        const uint32_t bBh = stg + (uint32_t)OFF_BHI * 2;
        const uint32_t bBl = stg + (uint32_t)OFF_BLO * 2;

        #pragma unroll
        for (int ks = 0; ks < 4; ++ks) {
            const int kk0 = ks * 16;
            uint32_t Ah[4][4], Al[4][4], Bh[4][4], Bl[4][4];
            #pragma unroll
            for (int mi = 0; mi < 4; ++mi) {
                uint32_t ar = (uint32_t)((wm * 64 + mi * 16 + rowselA) * ASTR
                                         + kk0 + colselA) * 2;
                ldmx4(Ah[mi], bAh + ar);
                ldmx4(Al[mi], bAl + ar);
            }
            #pragma unroll
            for (int nip = 0; nip < 4; ++nip) {
                uint32_t br = (uint32_t)((wn * 64 + nip * 16 + bcolsel) * ASTR
                                         + kk0 + bksel) * 2;
                ldmx4(Bh[nip], bBh + br);
                ldmx4(Bl[nip], bBl + br);
            }
            #pragma unroll
            for (int mi = 0; mi < 4; ++mi)
                #pragma unroll
                for (int ni = 0; ni < 8; ++ni) {
                    const uint32_t* bh = &Bh[ni >> 1][(ni & 1) * 2];
                    const uint32_t* bl = &Bl[ni >> 1][(ni & 1) * 2];
                    mma16816(acc[mi][ni], Ah[mi], bh);
                    mma16816(acc[mi][ni], Ah[mi], bl);
                    mma16816(acc[mi][ni], Al[mi], bh);
                }
        }
        __syncthreads();
    }

    #pragma unroll
    for (int mi = 0; mi < 4; ++mi) {
        int rm = m0 + wm * 64 + mi * 16 + g;
        #pragma unroll
        for (int ni = 0; ni < 8; ++ni) {
            int cn = n0 + wn * 64 + ni * 8 + 2 * tig;
            *(float2*)(C + (size_t)rm * N + cn) =
                make_float2(acc[mi][ni][0], acc[mi][ni][1]);
            *(float2*)(C + (size_t)(rm + 8) * N + cn) =
                make_float2(acc[mi][ni][2], acc[mi][ni][3]);
        }
    }
}

// ---------------------------------------------------------------------------
// fp16 single-pass GEMM (output projection): CTA 256x128, warp 64x64, BK=64.
// ---------------------------------------------------------------------------
#define FOFF_B (256*ASTR)
#define FSTG (384*ASTR)            // halfs per stage = 27648
#define GEMMH_SMEM (2*FSTG*2)      // 110592 bytes

__global__ __launch_bounds__(256, 1)
void gemm_f16_kernel(float* __restrict__ C,
    const __half* __restrict__ A, const __half* __restrict__ Bm,
    int M, int N, int K)
{
    extern __shared__ __half smh[];
    const uint32_t smem_base = smem_u32(smh);
    const int tid = threadIdx.x;
    const int wid = tid >> 5, lane = tid & 31;
    const int g = lane >> 2, tig = lane & 3;
    const int wm = wid >> 1, wn = wid & 1;
    const int m0 = blockIdx.y * 256, n0 = blockIdx.x * 128;
    const int nch = K >> 6;

    const int rowselA = ((lane >> 3) & 1) * 8 + (lane & 7);
    const int colselA = ((lane >> 4) & 1) * 8;
    const int bcolsel = ((lane >> 4) & 1) * 8 + (lane & 7);
    const int bksel   = ((lane >> 3) & 1) * 8;

    auto load_chunk = [&](int c, int stage) {
        const int k0 = c << 6;
        const uint32_t sb = smem_base + (uint32_t)(stage * FSTG) * 2;
        #pragma unroll
        for (int i = 0; i < 8; ++i) {
            int v = i * 256 + tid; int r = v >> 3, ch = v & 7;
            cp16(sb + (uint32_t)(r * ASTR + ch * 8) * 2,
                 A + (size_t)(m0 + r) * K + k0 + ch * 8);
        }
        #pragma unroll
        for (int i = 0; i < 4; ++i) {
            int v = i * 256 + tid; int r = v >> 3, ch = v & 7;
            cp16(sb + (uint32_t)(FOFF_B + r * ASTR + ch * 8) * 2,
                 Bm + (size_t)(n0 + r) * K + k0 + ch * 8);
        }
    };

    float acc[4][8][4];
    #pragma unroll
    for (int mi = 0; mi < 4; mi++)
        #pragma unroll
        for (int ni = 0; ni < 8; ni++)
            #pragma unroll
            for (int r = 0; r < 4; r++) acc[mi][ni][r] = 0.f;

    load_chunk(0, 0);
    CP_COMMIT();

    for (int c = 0; c < nch; ++c) {
        if (c + 1 < nch) { load_chunk(c + 1, (c + 1) & 1); CP_COMMIT(); CP_WAIT(1); }
        else             { CP_WAIT(0); }
        __syncthreads();

        const uint32_t stg = smem_base + (uint32_t)((c & 1) * FSTG) * 2;
        const uint32_t bA = stg;
        const uint32_t bB = stg + (uint32_t)FOFF_B * 2;

        #pragma unroll
        for (int ks = 0; ks < 4; ++ks) {
            const int kk0 = ks * 16;
            uint32_t Ah[4][4], Bh[4][4];
            #pragma unroll
            for (int mi = 0; mi < 4; ++mi) {
                uint32_t ar = (uint32_t)((wm * 64 + mi * 16 + rowselA) * ASTR
                                         + kk0 + colselA) * 2;
                ldmx4(Ah[mi], bA + ar);
            }
            #pragma unroll
            for (int nip = 0; nip < 4; ++nip) {
                uint32_t br = (uint32_t)((wn * 64 + nip * 16 + bcolsel) * ASTR
                                         + kk0 + bksel) * 2;
                ldmx4(Bh[nip], bB + br);
            }
            #pragma unroll
            for (int mi = 0; mi < 4; ++mi)
                #pragma unroll
                for (int ni = 0; ni < 8; ++ni)
                    mma16816h(acc[mi][ni], Ah[mi], &Bh[ni >> 1][(ni & 1) * 2]);
        }
        __syncthreads();
    }

    #pragma unroll
    for (int mi = 0; mi < 4; ++mi) {
        int rm = m0 + wm * 64 + mi * 16 + g;
        #pragma unroll
        for (int ni = 0; ni < 8; ++ni) {
            int cn = n0 + wn * 64 + ni * 8 + 2 * tig;
            *(float2*)(C + (size_t)rm * N + cn) =
                make_float2(acc[mi][ni][0], acc[mi][ni][1]);
            *(float2*)(C + (size_t)(rm + 8) * N + cn) =
                make_float2(acc[mi][ni][2], acc[mi][ni][3]);
        }
    }
}

// ---------------------------------------------------------------------------
// All-fp16 FA2 flash attention: single-pass QK^T and PV.
// FM=128 q-rows/CTA, FN=64 keys/tile, 256 threads (8 warps x 16 rows).
// smem: Q16 (34816) + 2 KV stages (34816 each) = 104448 bytes.
// ---------------------------------------------------------------------------
#define QSF 136
#define STG_KV (2*64*QSF*2)           // 34816 bytes per stage (K + V)
#define OFF_KV (128*QSF*2)            // 34816
#define FLASH_SMEM (OFF_KV + 2*STG_KV)   // 104448 bytes

__global__ __launch_bounds__(256) void flash_hmma_kernel(
    const __half* __restrict__ Q16, const __half* __restrict__ K16,
    const __half* __restrict__ V16, __half* __restrict__ O16)
{
    const int m_tile = gridDim.x - 1 - blockIdx.x;   // heavy CTAs first
    const int h = blockIdx.y;
    const int b = blockIdx.z;
    const int kvh = h / GROUPS;
    const int tid = threadIdx.x;
    const int warp = tid >> 5, lane = tid & 31;
    const int g = lane >> 2, tig = lane & 3;
    const int m0 = m_tile * 128;
    const int wrow = warp * 16;

    extern __shared__ char smc[];
    const uint32_t base = smem_u32(smc);

    const int rowselA = ((lane >> 3) & 1) * 8 + (lane & 7);
    const int colselA = ((lane >> 4) & 1) * 8;
    const int bcolsel = ((lane >> 4) & 1) * 8 + (lane & 7);
    const int bksel   = ((lane >> 3) & 1) * 8;
    const uint32_t voff = (uint32_t)(((lane & 7) + ((lane >> 3) & 1) * 8) * QSF
                                     + (lane >> 4) * 8);

    auto load_kv = [&](int nt, int stage) {
        const int n0 = nt * 64;
        const uint32_t sb = base + OFF_KV + (uint32_t)stage * STG_KV;
        #pragma unroll
        for (int i = 0; i < 8; ++i) {
            int v = i * 256 + tid;            // 0..2047
            int mat = v >> 10;                // 0..1 (K, V)
            int r = (v >> 4) & 63;
            int ch = v & 15;
            const __half* src = (mat ? V16 : K16)
                + (((size_t)b * S + n0 + r) * KVH + kvh) * HD + ch * 8;
            cp16(sb + (uint32_t)(mat * (64 * QSF) + r * QSF + ch * 8) * 2, src);
        }
    };

    // Q tile load (fp16, single)
    #pragma unroll
    for (int i = 0; i < 8; ++i) {
        int v = i * 256 + tid;               // 0..2047
        int r = v >> 4;
        int ch = v & 15;
        const __half* src = Q16 + (((size_t)b * S + m0 + r) * H + h) * HD + ch * 8;
        cp16(base + (uint32_t)(r * QSF + ch * 8) * 2, src);
    }
    load_kv(0, 0);
    CP_COMMIT();

    float acc[16][4];
    #pragma unroll
    for (int ni = 0; ni < 16; ++ni)
        #pragma unroll
        for (int r = 0; r < 4; ++r) acc[ni][r] = 0.f;

    float m_run0 = -1e30f, m_run1 = -1e30f;
    float l_run0 = 0.f, l_run1 = 0.f;

    const int ntmax = 2 * m_tile + 1;
    for (int nt = 0; nt <= ntmax; ++nt) {
        const int n0 = nt * 64;
        if (nt < ntmax) { load_kv(nt + 1, (nt + 1) & 1); CP_COMMIT(); CP_WAIT(1); }
        else            { CP_WAIT(0); }
        __syncthreads();

        const uint32_t kvb = base + OFF_KV + (uint32_t)(nt & 1) * STG_KV;
        const uint32_t bK = kvb;
        const uint32_t bV = kvb + (uint32_t)(64 * QSF) * 2;

        // ---- S = Q @ K^T (fp16 single-pass) ----
        float cs[8][4];
        #pragma unroll
        for (int ni = 0; ni < 8; ++ni)
            #pragma unroll
            for (int r = 0; r < 4; ++r) cs[ni][r] = 0.f;

        #pragma unroll
        for (int ks = 0; ks < 8; ++ks) {
            const int kk0 = ks * 16;
            uint32_t qh[4];
            ldmx4(qh, base + (uint32_t)((wrow + rowselA) * QSF + kk0 + colselA) * 2);
            #pragma unroll
            for (int nip = 0; nip < 4; ++nip) {
                uint32_t kh[4];
                ldmx4(kh, bK + (uint32_t)((nip * 16 + bcolsel) * QSF + kk0 + bksel) * 2);
                mma16816h(cs[2 * nip],     qh, kh);
                mma16816h(cs[2 * nip + 1], qh, kh + 2);
            }
        }

        // ---- causal mask ----
        const int r0g = m0 + wrow + g;
        const int colb = n0 + 2 * tig;
        #pragma unroll
        for (int ni = 0; ni < 8; ++ni) {
            int c = colb + ni * 8;
            if (c > r0g)         cs[ni][0] = -1e30f;
            if (c + 1 > r0g)     cs[ni][1] = -1e30f;
            if (c > r0g + 8)     cs[ni][2] = -1e30f;
            if (c + 1 > r0g + 8) cs[ni][3] = -1e30f;
        }

        // ---- register softmax ----
        float mx0 = -1e30f, mx1 = -1e30f;
        #pragma unroll
        for (int ni = 0; ni < 8; ++ni) {
            mx0 = fmaxf(mx0, fmaxf(cs[ni][0], cs[ni][1]));
            mx1 = fmaxf(mx1, fmaxf(cs[ni][2], cs[ni][3]));
        }
        mx0 = fmaxf(mx0, __shfl_xor_sync(0xFFFFFFFFu, mx0, 1));
        mx0 = fmaxf(mx0, __shfl_xor_sync(0xFFFFFFFFu, mx0, 2));
        mx1 = fmaxf(mx1, __shfl_xor_sync(0xFFFFFFFFu, mx1, 1));
        mx1 = fmaxf(mx1, __shfl_xor_sync(0xFFFFFFFFu, mx1, 2));
        const float mn0 = fmaxf(m_run0, mx0);
        const float mn1 = fmaxf(m_run1, mx1);
        const float corr0 = __expf(m_run0 - mn0);
        const float corr1 = __expf(m_run1 - mn1);
        float sum0 = 0.f, sum1 = 0.f;
        #pragma unroll
        for (int ni = 0; ni < 8; ++ni) {
            cs[ni][0] = __expf(cs[ni][0] - mn0); sum0 += cs[ni][0];
            cs[ni][1] = __expf(cs[ni][1] - mn0); sum0 += cs[ni][1];
            cs[ni][2] = __expf(cs[ni][2] - mn1); sum1 += cs[ni][2];
            cs[ni][3] = __expf(cs[ni][3] - mn1); sum1 += cs[ni][3];
        }
        sum0 += __shfl_xor_sync(0xFFFFFFFFu, sum0, 1);
        sum0 += __shfl_xor_sync(0xFFFFFFFFu, sum0, 2);
        sum1 += __shfl_xor_sync(0xFFFFFFFFu, sum1, 1);
        sum1 += __shfl_xor_sync(0xFFFFFFFFu, sum1, 2);
        l_run0 = l_run0 * corr0 + sum0;
        l_run1 = l_run1 * corr1 + sum1;
        m_run0 = mn0;
        m_run1 = mn1;
        #pragma unroll
        for (int ni = 0; ni < 16; ++ni) {
            acc[ni][0] *= corr0; acc[ni][1] *= corr0;
            acc[ni][2] *= corr1; acc[ni][3] *= corr1;
        }

        // ---- O += P @ V (fp16 single-pass) ----
        #pragma unroll
        for (int kp = 0; kp < 4; ++kp) {
            uint32_t ap[4];
            #pragma unroll
            for (int t = 0; t < 4; ++t) {
                int nn = 2 * kp + (t >> 1);
                int j0 = (t & 1) * 2;
                __half2 p = __floats2half2_rn(cs[nn][j0], cs[nn][j0 + 1]);
                ap[t] = *reinterpret_cast<uint32_t*>(&p);
            }
            #pragma unroll
            for (int np = 0; np < 8; ++np) {
                uint32_t bh[4];
                ldmx4t(bh, bV + (uint32_t)(voff + kp * 16 * QSF + np * 16) * 2);
                mma16816h(acc[2 * np],     ap, bh);
                mma16816h(acc[2 * np + 1], ap, bh + 2);
            }
        }
        __syncthreads();
    }

    const float inv0 = 1.f / l_run0;
    const float inv1 = 1.f / l_run1;
    const size_t row0 = (size_t)b * S + m0 + wrow + g;
    __half* o0 = O16 + row0 * (H * HD) + h * HD;
    __half* o1 = o0 + 8 * (size_t)(H * HD);
    #pragma unroll
    for (int ni = 0; ni < 16; ++ni) {
        int c = ni * 8 + 2 * tig;
        *(__half2*)(o0 + c) = __floats2half2_rn(acc[ni][0] * inv0, acc[ni][1] * inv0);
        *(__half2*)(o1 + c) = __floats2half2_rn(acc[ni][2] * inv1, acc[ni][3] * inv1);
    }
}

// ---------------------------------------------------------------------------
extern "C" void kernel_launch(void* const* d_in, const int* in_sizes, int n_in,
                              void* d_out, int out_size)
{
    const float* x    = (const float*)d_in[0];
    const float* cosb = (const float*)d_in[1];
    const float* sinb = (const float*)d_in[2];
    const float* Wq   = (const float*)d_in[4];
    const float* Wk   = (const float*)d_in[5];
    const float* Wv   = (const float*)d_in[6];
    const float* Wo   = (const float*)d_in[7];
    float* out = (float*)d_out;

    float* QKVp;
    cudaGetSymbolAddress((void**)&QKVp, g_QKV);
    __nv_bfloat16 *xhi, *xlo, *wqkvh, *wqkvl;
    __half *wo16, *o16, *q16, *k16, *v16;
    cudaGetSymbolAddress((void**)&xhi, g_xhi);
    cudaGetSymbolAddress((void**)&xlo, g_xlo);
    cudaGetSymbolAddress((void**)&wqkvh, g_WqkvT_hi);
    cudaGetSymbolAddress((void**)&wqkvl, g_WqkvT_lo);
    cudaGetSymbolAddress((void**)&wo16, g_Wo16T);
    cudaGetSymbolAddress((void**)&o16, g_O16);
    cudaGetSymbolAddress((void**)&q16, g_Q16);
    cudaGetSymbolAddress((void**)&k16, g_K16);
    cudaGetSymbolAddress((void**)&v16, g_V16);

    const int M = M_ROWS;  // 4096

    // prep
    split_kernel<<<(M * D / 4) / 256, 256>>>(x, xhi, xlo, M * D / 4);
    transpose_split_kernel<<<dim3(D / 32, D / 32), dim3(32, 8)>>>(
        Wq, wqkvh, wqkvl, nullptr, nullptr, nullptr, D, H * HD);
    transpose_split_kernel<<<dim3((KVH * HD) / 32, D / 32, 2), dim3(32, 8)>>>(
        Wk, wqkvh + (size_t)(H * HD) * D, wqkvl + (size_t)(H * HD) * D,
        Wv, wqkvh + (size_t)(H * HD + KVH * HD) * D,
            wqkvl + (size_t)(H * HD + KVH * HD) * D, D, KVH * HD);
    transpose_convert_kernel<<<dim3(D / 32, (H * HD) / 32), dim3(32, 8)>>>(
        Wo, wo16, H * HD, D);

    cudaFuncSetAttribute(gemm_bf16x3_kernel,
                         cudaFuncAttributeMaxDynamicSharedMemorySize, GEMM_SMEM);
    cudaFuncSetAttribute(gemm_f16_kernel,
                         cudaFuncAttributeMaxDynamicSharedMemorySize, GEMMH_SMEM);

    // fused QKV projection: [4096, 3072] (bf16x3, precision-critical path)
    gemm_bf16x3_kernel<<<dim3(NQKV / 128, M / 256), 256, GEMM_SMEM>>>(
        QKVp, xhi, xlo, wqkvh, wqkvl, M, NQKV, D);

    // rope + convert to fp16 (Q scaled); V strided convert
    rope_f16_kernel<<<(B * S * H * 64) / 256, 256>>>(
        QKVp, cosb, sinb, q16, SCALE, H, NQKV, 0);
    rope_f16_kernel<<<(B * S * KVH * 64) / 256, 256>>>(
        QKVp, cosb, sinb, k16, 1.0f, KVH, NQKV, H * HD);
    convert_strided_kernel<<<(M * KVH * HD / 4) / 256, 256>>>(
        QKVp, v16, KVH * HD, NQKV, H * HD + KVH * HD, M * KVH * HD / 4);

    // all-fp16 flash attention
    cudaFuncSetAttribute(flash_hmma_kernel,
                         cudaFuncAttributeMaxDynamicSharedMemorySize, FLASH_SMEM);
    flash_hmma_kernel<<<dim3(S / 128, H, B), 256, FLASH_SMEM>>>(
        q16, k16, v16, o16);

    // output projection: fp16 single-pass
    gemm_f16_kernel<<<dim3(D / 128, M / 256), 256, GEMMH_SMEM>>>(
        out, o16, wo16, M, D, D);
}

// round 15
// speedup vs baseline: 2.2891x; 1.5052x over previous
#include <cuda_runtime.h>
#include <cuda_fp16.h>
#include <math.h>
#include <stdint.h>

#define B 2
#define S 2048
#define D 2048
#define H 16
#define KVH 4
#define HD 128
#define GROUPS (H/KVH)
#define SCALE 0.08838834764831845f
#define M_ROWS (B*S)          // 4096
#define NQKV (H*HD + 2*KVH*HD)   // 3072

// ---------------- scratch (__device__ globals; no allocation) --------------
__device__ float g_QKV[M_ROWS*NQKV];           // fused projection output (fp32)

__device__ __half g_x16[M_ROWS*D];
__device__ __half g_Wqkv16T[NQKV*D];           // [3072, 2048] fp16
__device__ __half g_Wo16T[D*H*HD];             // [2048, 2048] fp16
__device__ __half g_O16[M_ROWS*D];             // flash output, fp16

__device__ __half g_Q16[B*S*H*HD];
__device__ __half g_K16[B*S*KVH*HD];
__device__ __half g_V16[B*S*KVH*HD];

// ---------------------------- helpers --------------------------------------
__device__ __forceinline__ uint32_t smem_u32(const void* p) {
    uint32_t a;
    asm("{ .reg .u64 t; cvta.to.shared.u64 t, %1; cvt.u32.u64 %0, t; }"
        : "=r"(a) : "l"(p));
    return a;
}
__device__ __forceinline__ void cp16(uint32_t s, const void* g) {
    asm volatile("cp.async.cg.shared.global [%0], [%1], 16;" :: "r"(s), "l"(g));
}
#define CP_COMMIT() asm volatile("cp.async.commit_group;" ::: "memory")
#define CP_WAIT(n)  asm volatile("cp.async.wait_group %0;" :: "n"(n) : "memory")

__device__ __forceinline__ void mma16816h(float* c, const uint32_t* a,
                                          const uint32_t* b) {
    asm volatile(
        "mma.sync.aligned.m16n8k16.row.col.f32.f16.f16.f32 "
        "{%0,%1,%2,%3}, {%4,%5,%6,%7}, {%8,%9}, {%0,%1,%2,%3};"
        : "+f"(c[0]), "+f"(c[1]), "+f"(c[2]), "+f"(c[3])
        : "r"(a[0]), "r"(a[1]), "r"(a[2]), "r"(a[3]), "r"(b[0]), "r"(b[1]));
}
__device__ __forceinline__ void ldmx4(uint32_t* r, uint32_t addr) {
    asm volatile("ldmatrix.sync.aligned.m8n8.x4.shared.b16 {%0,%1,%2,%3}, [%4];"
        : "=r"(r[0]), "=r"(r[1]), "=r"(r[2]), "=r"(r[3]) : "r"(addr));
}
__device__ __forceinline__ void ldmx4t(uint32_t* r, uint32_t addr) {
    asm volatile("ldmatrix.sync.aligned.m8n8.x4.trans.shared.b16 "
                 "{%0,%1,%2,%3}, [%4];"
        : "=r"(r[0]), "=r"(r[1]), "=r"(r[2]), "=r"(r[3]) : "r"(addr));
}

// ---------------------------------------------------------------------------
// convert: fp32 packed -> fp16 packed
// ---------------------------------------------------------------------------
__global__ void convert_kernel(const float* __restrict__ X,
                               __half* __restrict__ out, int n4)
{
    int i = blockIdx.x * blockDim.x + threadIdx.x;
    if (i >= n4) return;
    float4 x = reinterpret_cast<const float4*>(X)[i];
    __half2 h0 = __floats2half2_rn(x.x, x.y);
    __half2 h1 = __floats2half2_rn(x.z, x.w);
    *reinterpret_cast<__half2*>(out + 4*(size_t)i) = h0;
    *reinterpret_cast<__half2*>(out + 4*(size_t)i + 2) = h1;
}

// ---------------------------------------------------------------------------
// strided convert: fp32 (strided rows) -> packed fp16 (for V slice)
// ---------------------------------------------------------------------------
__global__ void convert_strided_kernel(const float* __restrict__ X,
                                       __half* __restrict__ out,
                                       int width, int srcstride, int coloff, int n4)
{
    int i = blockIdx.x * blockDim.x + threadIdx.x;
    if (i >= n4) return;
    int e0 = i * 4;
    int row = e0 / width, col = e0 % width;
    const float* src = X + (size_t)row * srcstride + coloff + col;
    float4 x = *reinterpret_cast<const float4*>(src);
    *reinterpret_cast<__half2*>(out + (size_t)e0) = __floats2half2_rn(x.x, x.y);
    *reinterpret_cast<__half2*>(out + (size_t)e0 + 2) = __floats2half2_rn(x.z, x.w);
}

// ---------------------------------------------------------------------------
// rope + convert to fp16 (+ optional scale), reading fused QKV buffer
// ---------------------------------------------------------------------------
__global__ void rope_f16_kernel(const float* __restrict__ X,
                                const float* __restrict__ cosb,
                                const float* __restrict__ sinb,
                                __half* __restrict__ out,
                                float scale, int nheads,
                                int rowstride, int coloff)
{
    int idx = blockIdx.x * blockDim.x + threadIdx.x;
    int half = idx & 63;
    int hrow = idx >> 6;
    int rowidx = hrow / nheads;
    int head = hrow - rowidx * nheads;
    int s = rowidx % S;
    const float* src = X + (size_t)rowidx * rowstride + coloff + head * HD;
    size_t dbase = (size_t)hrow * HD;
    float x0 = src[half];
    float x1 = src[half + 64];
    float c0 = cosb[s * 64 + (half >> 1)];
    float s0 = sinb[s * 64 + (half >> 1)];
    float c1 = cosb[s * 64 + ((half + 64) >> 1)];
    float s1 = sinb[s * 64 + ((half + 64) >> 1)];
    out[dbase + half]      = __float2half_rn((x0 * c0 - x1 * s0) * scale);
    out[dbase + half + 64] = __float2half_rn((x1 * c1 + x0 * s1) * scale);
}

// ---------------------------------------------------------------------------
// transpose + convert: W [R, C] fp32 -> T [C, R] fp16 (z: up to 2 pairs)
// ---------------------------------------------------------------------------
__global__ void transpose_convert_kernel(const float* __restrict__ W0,
                                         __half* __restrict__ T0,
                                         const float* __restrict__ W1,
                                         __half* __restrict__ T1,
                                         int R, int C)
{
    const float* W = blockIdx.z ? W1 : W0;
    __half* T = blockIdx.z ? T1 : T0;
    __shared__ float t[32][33];
    int c0 = blockIdx.x * 32, r0 = blockIdx.y * 32;
    int tx = threadIdx.x, ty = threadIdx.y;
    #pragma unroll
    for (int i = 0; i < 32; i += 8)
        t[ty + i][tx] = W[(size_t)(r0 + ty + i) * C + c0 + tx];
    __syncthreads();
    #pragma unroll
    for (int i = 0; i < 32; i += 8)
        T[(size_t)(c0 + ty + i) * R + r0 + tx] = __float2half_rn(t[tx][ty + i]);
}

// ---------------------------------------------------------------------------
// fp16 single-pass GEMM: CTA 256x128, 8 warps (4x2), warp tile 64x64, BK=64,
// 2-stage cp.async, ldmatrix fragments. C[M,N] = A[M,K] @ Bm[N,K]^T, fp32 out.
// ---------------------------------------------------------------------------
#define ASTR 72
#define FOFF_B (256*ASTR)
#define FSTG (384*ASTR)            // halfs per stage = 27648
#define GEMMH_SMEM (2*FSTG*2)      // 110592 bytes

__global__ __launch_bounds__(256, 1)
void gemm_f16_kernel(float* __restrict__ C,
    const __half* __restrict__ A, const __half* __restrict__ Bm,
    int M, int N, int K)
{
    extern __shared__ __half smh[];
    const uint32_t smem_base = smem_u32(smh);
    const int tid = threadIdx.x;
    const int wid = tid >> 5, lane = tid & 31;
    const int g = lane >> 2, tig = lane & 3;
    const int wm = wid >> 1, wn = wid & 1;
    const int m0 = blockIdx.y * 256, n0 = blockIdx.x * 128;
    const int nch = K >> 6;

    const int rowselA = ((lane >> 3) & 1) * 8 + (lane & 7);
    const int colselA = ((lane >> 4) & 1) * 8;
    const int bcolsel = ((lane >> 4) & 1) * 8 + (lane & 7);
    const int bksel   = ((lane >> 3) & 1) * 8;

    auto load_chunk = [&](int c, int stage) {
        const int k0 = c << 6;
        const uint32_t sb = smem_base + (uint32_t)(stage * FSTG) * 2;
        #pragma unroll
        for (int i = 0; i < 8; ++i) {
            int v = i * 256 + tid; int r = v >> 3, ch = v & 7;
            cp16(sb + (uint32_t)(r * ASTR + ch * 8) * 2,
                 A + (size_t)(m0 + r) * K + k0 + ch * 8);
        }
        #pragma unroll
        for (int i = 0; i < 4; ++i) {
            int v = i * 256 + tid; int r = v >> 3, ch = v & 7;
            cp16(sb + (uint32_t)(FOFF_B + r * ASTR + ch * 8) * 2,
                 Bm + (size_t)(n0 + r) * K + k0 + ch * 8);
        }
    };

    float acc[4][8][4];
    #pragma unroll
    for (int mi = 0; mi < 4; mi++)
        #pragma unroll
        for (int ni = 0; ni < 8; ni++)
            #pragma unroll
            for (int r = 0; r < 4; r++) acc[mi][ni][r] = 0.f;

    load_chunk(0, 0);
    CP_COMMIT();

    for (int c = 0; c < nch; ++c) {
        if (c + 1 < nch) { load_chunk(c + 1, (c + 1) & 1); CP_COMMIT(); CP_WAIT(1); }
        else             { CP_WAIT(0); }
        __syncthreads();

        const uint32_t stg = smem_base + (uint32_t)((c & 1) * FSTG) * 2;
        const uint32_t bA = stg;
        const uint32_t bB = stg + (uint32_t)FOFF_B * 2;

        #pragma unroll
        for (int ks = 0; ks < 4; ++ks) {
            const int kk0 = ks * 16;
            uint32_t Ah[4][4], Bh[4][4];
            #pragma unroll
            for (int mi = 0; mi < 4; ++mi) {
                uint32_t ar = (uint32_t)((wm * 64 + mi * 16 + rowselA) * ASTR
                                         + kk0 + colselA) * 2;
                ldmx4(Ah[mi], bA + ar);
            }
            #pragma unroll
            for (int nip = 0; nip < 4; ++nip) {
                uint32_t br = (uint32_t)((wn * 64 + nip * 16 + bcolsel) * ASTR
                                         + kk0 + bksel) * 2;
                ldmx4(Bh[nip], bB + br);
            }
            #pragma unroll
            for (int mi = 0; mi < 4; ++mi)
                #pragma unroll
                for (int ni = 0; ni < 8; ++ni)
                    mma16816h(acc[mi][ni], Ah[mi], &Bh[ni >> 1][(ni & 1) * 2]);
        }
        __syncthreads();
    }

    #pragma unroll
    for (int mi = 0; mi < 4; ++mi) {
        int rm = m0 + wm * 64 + mi * 16 + g;
        #pragma unroll
        for (int ni = 0; ni < 8; ++ni) {
            int cn = n0 + wn * 64 + ni * 8 + 2 * tig;
            *(float2*)(C + (size_t)rm * N + cn) =
                make_float2(acc[mi][ni][0], acc[mi][ni][1]);
            *(float2*)(C + (size_t)(rm + 8) * N + cn) =
                make_float2(acc[mi][ni][2], acc[mi][ni][3]);
        }
    }
}

// ---------------------------------------------------------------------------
// All-fp16 FA2 flash attention: single-pass QK^T and PV.
// FM=128 q-rows/CTA, FN=64 keys/tile, 256 threads (8 warps x 16 rows).
// ---------------------------------------------------------------------------
#define QSF 136
#define STG_KV (2*64*QSF*2)           // 34816 bytes per stage (K + V)
#define OFF_KV (128*QSF*2)            // 34816
#define FLASH_SMEM (OFF_KV + 2*STG_KV)   // 104448 bytes

__global__ __launch_bounds__(256) void flash_hmma_kernel(
    const __half* __restrict__ Q16, const __half* __restrict__ K16,
    const __half* __restrict__ V16, __half* __restrict__ O16)
{
    const int m_tile = gridDim.x - 1 - blockIdx.x;   // heavy CTAs first
    const int h = blockIdx.y;
    const int b = blockIdx.z;
    const int kvh = h / GROUPS;
    const int tid = threadIdx.x;
    const int warp = tid >> 5, lane = tid & 31;
    const int g = lane >> 2, tig = lane & 3;
    const int m0 = m_tile * 128;
    const int wrow = warp * 16;

    extern __shared__ char smc[];
    const uint32_t base = smem_u32(smc);

    const int rowselA = ((lane >> 3) & 1) * 8 + (lane & 7);
    const int colselA = ((lane >> 4) & 1) * 8;
    const int bcolsel = ((lane >> 4) & 1) * 8 + (lane & 7);
    const int bksel   = ((lane >> 3) & 1) * 8;
    const uint32_t voff = (uint32_t)(((lane & 7) + ((lane >> 3) & 1) * 8) * QSF
                                     + (lane >> 4) * 8);

    auto load_kv = [&](int nt, int stage) {
        const int n0 = nt * 64;
        const uint32_t sb = base + OFF_KV + (uint32_t)stage * STG_KV;
        #pragma unroll
        for (int i = 0; i < 8; ++i) {
            int v = i * 256 + tid;
            int mat = v >> 10;
            int r = (v >> 4) & 63;
            int ch = v & 15;
            const __half* src = (mat ? V16 : K16)
                + (((size_t)b * S + n0 + r) * KVH + kvh) * HD + ch * 8;
            cp16(sb + (uint32_t)(mat * (64 * QSF) + r * QSF + ch * 8) * 2, src);
        }
    };

    #pragma unroll
    for (int i = 0; i < 8; ++i) {
        int v = i * 256 + tid;
        int r = v >> 4;
        int ch = v & 15;
        const __half* src = Q16 + (((size_t)b * S + m0 + r) * H + h) * HD + ch * 8;
        cp16(base + (uint32_t)(r * QSF + ch * 8) * 2, src);
    }
    load_kv(0, 0);
    CP_COMMIT();

    float acc[16][4];
    #pragma unroll
    for (int ni = 0; ni < 16; ++ni)
        #pragma unroll
        for (int r = 0; r < 4; ++r) acc[ni][r] = 0.f;

    float m_run0 = -1e30f, m_run1 = -1e30f;
    float l_run0 = 0.f, l_run1 = 0.f;

    const int ntmax = 2 * m_tile + 1;
    for (int nt = 0; nt <= ntmax; ++nt) {
        const int n0 = nt * 64;
        if (nt < ntmax) { load_kv(nt + 1, (nt + 1) & 1); CP_COMMIT(); CP_WAIT(1); }
        else            { CP_WAIT(0); }
        __syncthreads();

        const uint32_t kvb = base + OFF_KV + (uint32_t)(nt & 1) * STG_KV;
        const uint32_t bK = kvb;
        const uint32_t bV = kvb + (uint32_t)(64 * QSF) * 2;

        float cs[8][4];
        #pragma unroll
        for (int ni = 0; ni < 8; ++ni)
            #pragma unroll
            for (int r = 0; r < 4; ++r) cs[ni][r] = 0.f;

        #pragma unroll
        for (int ks = 0; ks < 8; ++ks) {
            const int kk0 = ks * 16;
            uint32_t qh[4];
            ldmx4(qh, base + (uint32_t)((wrow + rowselA) * QSF + kk0 + colselA) * 2);
            #pragma unroll
            for (int nip = 0; nip < 4; ++nip) {
                uint32_t kh[4];
                ldmx4(kh, bK + (uint32_t)((nip * 16 + bcolsel) * QSF + kk0 + bksel) * 2);
                mma16816h(cs[2 * nip],     qh, kh);
                mma16816h(cs[2 * nip + 1], qh, kh + 2);
            }
        }

        const int r0g = m0 + wrow + g;
        const int colb = n0 + 2 * tig;
        #pragma unroll
        for (int ni = 0; ni < 8; ++ni) {
            int c = colb + ni * 8;
            if (c > r0g)         cs[ni][0] = -1e30f;
            if (c + 1 > r0g)     cs[ni][1] = -1e30f;
            if (c > r0g + 8)     cs[ni][2] = -1e30f;
            if (c + 1 > r0g + 8) cs[ni][3] = -1e30f;
        }

        float mx0 = -1e30f, mx1 = -1e30f;
        #pragma unroll
        for (int ni = 0; ni < 8; ++ni) {
            mx0 = fmaxf(mx0, fmaxf(cs[ni][0], cs[ni][1]));
            mx1 = fmaxf(mx1, fmaxf(cs[ni][2], cs[ni][3]));
        }
        mx0 = fmaxf(mx0, __shfl_xor_sync(0xFFFFFFFFu, mx0, 1));
        mx0 = fmaxf(mx0, __shfl_xor_sync(0xFFFFFFFFu, mx0, 2));
        mx1 = fmaxf(mx1, __shfl_xor_sync(0xFFFFFFFFu, mx1, 1));
        mx1 = fmaxf(mx1, __shfl_xor_sync(0xFFFFFFFFu, mx1, 2));
        const float mn0 = fmaxf(m_run0, mx0);
        const float mn1 = fmaxf(m_run1, mx1);
        const float corr0 = __expf(m_run0 - mn0);
        const float corr1 = __expf(m_run1 - mn1);
        float sum0 = 0.f, sum1 = 0.f;
        #pragma unroll
        for (int ni = 0; ni < 8; ++ni) {
            cs[ni][0] = __expf(cs[ni][0] - mn0); sum0 += cs[ni][0];
            cs[ni][1] = __expf(cs[ni][1] - mn0); sum0 += cs[ni][1];
            cs[ni][2] = __expf(cs[ni][2] - mn1); sum1 += cs[ni][2];
            cs[ni][3] = __expf(cs[ni][3] - mn1); sum1 += cs[ni][3];
        }
        sum0 += __shfl_xor_sync(0xFFFFFFFFu, sum0, 1);
        sum0 += __shfl_xor_sync(0xFFFFFFFFu, sum0, 2);
        sum1 += __shfl_xor_sync(0xFFFFFFFFu, sum1, 1);
        sum1 += __shfl_xor_sync(0xFFFFFFFFu, sum1, 2);
        l_run0 = l_run0 * corr0 + sum0;
        l_run1 = l_run1 * corr1 + sum1;
        m_run0 = mn0;
        m_run1 = mn1;
        #pragma unroll
        for (int ni = 0; ni < 16; ++ni) {
            acc[ni][0] *= corr0; acc[ni][1] *= corr0;
            acc[ni][2] *= corr1; acc[ni][3] *= corr1;
        }

        #pragma unroll
        for (int kp = 0; kp < 4; ++kp) {
            uint32_t ap[4];
            #pragma unroll
            for (int t = 0; t < 4; ++t) {
                int nn = 2 * kp + (t >> 1);
                int j0 = (t & 1) * 2;
                __half2 p = __floats2half2_rn(cs[nn][j0], cs[nn][j0 + 1]);
                ap[t] = *reinterpret_cast<uint32_t*>(&p);
            }
            #pragma unroll
            for (int np = 0; np < 8; ++np) {
                uint32_t bh[4];
                ldmx4t(bh, bV + (uint32_t)(voff + kp * 16 * QSF + np * 16) * 2);
                mma16816h(acc[2 * np],     ap, bh);
                mma16816h(acc[2 * np + 1], ap, bh + 2);
            }
        }
        __syncthreads();
    }

    const float inv0 = 1.f / l_run0;
    const float inv1 = 1.f / l_run1;
    const size_t row0 = (size_t)b * S + m0 + wrow + g;
    __half* o0 = O16 + row0 * (H * HD) + h * HD;
    __half* o1 = o0 + 8 * (size_t)(H * HD);
    #pragma unroll
    for (int ni = 0; ni < 16; ++ni) {
        int c = ni * 8 + 2 * tig;
        *(__half2*)(o0 + c) = __floats2half2_rn(acc[ni][0] * inv0, acc[ni][1] * inv0);
        *(__half2*)(o1 + c) = __floats2half2_rn(acc[ni][2] * inv1, acc[ni][3] * inv1);
    }
}

// ---------------------------------------------------------------------------
extern "C" void kernel_launch(void* const* d_in, const int* in_sizes, int n_in,
                              void* d_out, int out_size)
{
    const float* x    = (const float*)d_in[0];
    const float* cosb = (const float*)d_in[1];
    const float* sinb = (const float*)d_in[2];
    const float* Wq   = (const float*)d_in[4];
    const float* Wk   = (const float*)d_in[5];
    const float* Wv   = (const float*)d_in[6];
    const float* Wo   = (const float*)d_in[7];
    float* out = (float*)d_out;

    float* QKVp;
    cudaGetSymbolAddress((void**)&QKVp, g_QKV);
    __half *x16, *wqkv16, *wo16, *o16, *q16, *k16, *v16;
    cudaGetSymbolAddress((void**)&x16, g_x16);
    cudaGetSymbolAddress((void**)&wqkv16, g_Wqkv16T);
    cudaGetSymbolAddress((void**)&wo16, g_Wo16T);
    cudaGetSymbolAddress((void**)&o16, g_O16);
    cudaGetSymbolAddress((void**)&q16, g_Q16);
    cudaGetSymbolAddress((void**)&k16, g_K16);
    cudaGetSymbolAddress((void**)&v16, g_V16);

    const int M = M_ROWS;  // 4096

    // prep: convert x to fp16; transpose+convert all weights
    convert_kernel<<<(M * D / 4) / 256, 256>>>(x, x16, M * D / 4);
    transpose_convert_kernel<<<dim3(D / 32, D / 32, 2), dim3(32, 8)>>>(
        Wq, wqkv16, Wo, wo16, D, H * HD);   // both are [2048, 2048]
    transpose_convert_kernel<<<dim3((KVH * HD) / 32, D / 32, 2), dim3(32, 8)>>>(
        Wk, wqkv16 + (size_t)(H * HD) * D,
        Wv, wqkv16 + (size_t)(H * HD + KVH * HD) * D, D, KVH * HD);

    cudaFuncSetAttribute(gemm_f16_kernel,
                         cudaFuncAttributeMaxDynamicSharedMemorySize, GEMMH_SMEM);

    // fused QKV projection: [4096, 3072], fp16 single-pass, fp32 out
    gemm_f16_kernel<<<dim3(NQKV / 128, M / 256), 256, GEMMH_SMEM>>>(
        QKVp, x16, wqkv16, M, NQKV, D);

    // rope + convert to fp16 (Q scaled); V strided convert
    rope_f16_kernel<<<(B * S * H * 64) / 256, 256>>>(
        QKVp, cosb, sinb, q16, SCALE, H, NQKV, 0);
    rope_f16_kernel<<<(B * S * KVH * 64) / 256, 256>>>(
        QKVp, cosb, sinb, k16, 1.0f, KVH, NQKV, H * HD);
    convert_strided_kernel<<<(M * KVH * HD / 4) / 256, 256>>>(
        QKVp, v16, KVH * HD, NQKV, H * HD + KVH * HD, M * KVH * HD / 4);

    // all-fp16 flash attention
    cudaFuncSetAttribute(flash_hmma_kernel,
                         cudaFuncAttributeMaxDynamicSharedMemorySize, FLASH_SMEM);
    flash_hmma_kernel<<<dim3(S / 128, H, B), 256, FLASH_SMEM>>>(
        q16, k16, v16, o16);

    // output projection: fp16 single-pass
    gemm_f16_kernel<<<dim3(D / 128, M / 256), 256, GEMMH_SMEM>>>(
        out, o16, wo16, M, D, D);
}